// round 1
// baseline (speedup 1.0000x reference)
#include <cuda_runtime.h>

#define N_NODES 50000
#define N_EDGES 800000
#define D 256
#define T_REP 4
#define NS 64
#define N_TOT (5 * N_NODES)                 /* 250000 */
#define NE_TOT (2 * N_EDGES + 3 * N_NODES)  /* 1750000 */

// ---------------- scratch (device globals; no allocation) ----------------
__device__ float g_AF[(size_t)N_TOT * D];   // all_features (rows 0..N: features, N..5N: transformed)
__device__ float g_X[(size_t)N_TOT * D];    // xw scratch
__device__ float g_B[(size_t)N_TOT * D];    // gcn output scratch (h1, then af2)
__device__ float g_invn[T_REP * N_NODES];   // 1/max(||transformed||,eps)
__device__ int   g_deg[N_TOT];
__device__ float g_dinv[N_TOT];
__device__ int   g_esrc[NE_TOT];
__device__ int   g_edst[NE_TOT];
__device__ float g_enorm[NE_TOT];
__device__ int   g_best[N_EDGES];
__device__ int   g_cls[N_TOT];
__device__ float g_zerobias[D];             // stays zero (zero-initialized, never written)

// ---------------- kernels ----------------

__global__ void k_copy_features(const float4* __restrict__ f) {
    int i = blockIdx.x * blockDim.x + threadIdx.x;
    if (i < N_NODES * D / 4) ((float4*)g_AF)[i] = f[i];
}

// C[M,256] = op(A[M,256]) @ W[256,256] + bias[256]; op = relu if RELU
template<int RELU>
__global__ __launch_bounds__(256) void k_sgemm(const float* __restrict__ A,
                                               const float* __restrict__ W,
                                               const float* __restrict__ bias,
                                               float* __restrict__ C, int M) {
    __shared__ float As[8][128];
    __shared__ float Bs[8][128];
    const int tid = threadIdx.x;
    const int tx = tid & 15, ty = tid >> 4;
    const int rowBase = blockIdx.y << 7;
    const int colBase = blockIdx.x << 7;
    float acc[8][8];
#pragma unroll
    for (int i = 0; i < 8; i++)
#pragma unroll
        for (int j = 0; j < 8; j++) acc[i][j] = 0.f;

    const int la_r = tid >> 1;
    const int la_k = (tid & 1) << 2;
    const int lb_k = tid >> 5;
    const int lb_c = (tid & 31) << 2;
    const int ar = rowBase + la_r;
    const bool aok = ar < M;

    for (int k0 = 0; k0 < 256; k0 += 8) {
        float4 av = make_float4(0.f, 0.f, 0.f, 0.f);
        if (aok) av = *(const float4*)(A + (size_t)ar * 256 + (k0 + la_k));
        if (RELU) {
            av.x = fmaxf(av.x, 0.f); av.y = fmaxf(av.y, 0.f);
            av.z = fmaxf(av.z, 0.f); av.w = fmaxf(av.w, 0.f);
        }
        float4 bv = *(const float4*)(W + (size_t)(k0 + lb_k) * 256 + colBase + lb_c);
        As[la_k + 0][la_r] = av.x; As[la_k + 1][la_r] = av.y;
        As[la_k + 2][la_r] = av.z; As[la_k + 3][la_r] = av.w;
        *(float4*)&Bs[lb_k][lb_c] = bv;
        __syncthreads();
#pragma unroll
        for (int k = 0; k < 8; k++) {
            float a[8], b[8];
#pragma unroll
            for (int i = 0; i < 8; i++) a[i] = As[k][(i << 4) + ty];
#pragma unroll
            for (int j = 0; j < 8; j++) b[j] = Bs[k][(j << 4) + tx];
#pragma unroll
            for (int i = 0; i < 8; i++)
#pragma unroll
                for (int j = 0; j < 8; j++) acc[i][j] = fmaf(a[i], b[j], acc[i][j]);
        }
        __syncthreads();
    }
#pragma unroll
    for (int i = 0; i < 8; i++) {
        int r = rowBase + (i << 4) + ty;
        if (r >= M) continue;
#pragma unroll
        for (int j = 0; j < 8; j++) {
            int c = colBase + (j << 4) + tx;
            C[(size_t)r * 256 + c] = acc[i][j] + bias[c];
        }
    }
}

__global__ void k_invnorm() {
    int warp = (blockIdx.x * blockDim.x + threadIdx.x) >> 5;
    int lane = threadIdx.x & 31;
    if (warp >= T_REP * N_NODES) return;
    const float4* r = (const float4*)(g_AF + ((size_t)N_NODES + warp) * 256);
    float4 a = r[lane * 2], b = r[lane * 2 + 1];
    float s = a.x * a.x + a.y * a.y + a.z * a.z + a.w * a.w +
              b.x * b.x + b.y * b.y + b.z * b.z + b.w * b.w;
#pragma unroll
    for (int o = 16; o; o >>= 1) s += __shfl_xor_sync(0xffffffffu, s, o);
    if (lane == 0) g_invn[warp] = 1.f / fmaxf(sqrtf(s), 1e-8f);
}

// per-edge argmax over t of dot(f[src], transformed_t[dst]) * invn  (src-norm is a common
// positive factor -> irrelevant for argmax)
__global__ void k_edge_sim(const int* __restrict__ ei) {
    int warp = (blockIdx.x * blockDim.x + threadIdx.x) >> 5;
    if (warp >= N_EDGES) return;
    int lane = threadIdx.x & 31;
    int s = ei[warp], d = ei[N_EDGES + warp];
    const float4* fr = (const float4*)(g_AF + (size_t)s * 256);
    float4 f0 = fr[lane * 2], f1 = fr[lane * 2 + 1];
    float bestv = -3.4e38f;
    int bi = 0;
#pragma unroll
    for (int t = 0; t < 4; t++) {
        const float4* tr = (const float4*)(g_AF + ((size_t)(t + 1) * N_NODES + d) * 256);
        float4 a = tr[lane * 2], b = tr[lane * 2 + 1];
        float p = f0.x * a.x + f0.y * a.y + f0.z * a.z + f0.w * a.w +
                  f1.x * b.x + f1.y * b.y + f1.z * b.z + f1.w * b.w;
#pragma unroll
        for (int o = 16; o; o >>= 1) p += __shfl_xor_sync(0xffffffffu, p, o);
        float sim = p * g_invn[t * N_NODES + d];
        if (sim > bestv) { bestv = sim; bi = t; }   // strict > == first-max (jnp.argmax)
    }
    if (lane == 0) g_best[warp] = bi;
}

__global__ void k_deg_init() {
    int i = blockIdx.x * blockDim.x + threadIdx.x;
    if (i < N_TOT) g_deg[i] = 1;   // self loop
}

__global__ void k_build_edges(const int* __restrict__ ei) {
    int i = blockIdx.x * blockDim.x + threadIdx.x;
    if (i >= NE_TOT) return;
    int s, d;
    if (i < N_EDGES) {
        s = ei[i]; d = ei[N_EDGES + i];
    } else if (i < 2 * N_EDGES) {
        int e = i - N_EDGES;
        s = ei[e]; d = ei[N_EDGES + e] + g_best[e] * N_NODES;
    } else {
        int r = i - 2 * N_EDGES;
        int rep = r / N_NODES + 1;            // 1..3 (rep 0 edges are self loops, weight 0)
        int n = r - (rep - 1) * N_NODES;
        s = n; d = n + rep * N_NODES;
    }
    g_esrc[i] = s; g_edst[i] = d;
    if (s != d) atomicAdd(&g_deg[d], 1);
}

__global__ void k_dinv() {
    int i = blockIdx.x * blockDim.x + threadIdx.x;
    if (i < N_TOT) g_dinv[i] = rsqrtf((float)g_deg[i]);
}

__global__ void k_enorm() {
    int i = blockIdx.x * blockDim.x + threadIdx.x;
    if (i >= NE_TOT) return;
    int s = g_esrc[i], d = g_edst[i];
    g_enorm[i] = (s == d) ? 0.f : g_dinv[s] * g_dinv[d];
}

// Out[j] = bias + dinv[j]^2 * X[j]   (self loop contribution + bias)
__global__ void k_gcn_init(const float* __restrict__ X, const float* __restrict__ bias,
                           float* __restrict__ Out) {
    int i = blockIdx.x * blockDim.x + threadIdx.x;
    if (i >= N_TOT * (D / 4)) return;
    int row = i >> 6, k4 = i & 63;
    float dv = g_dinv[row];
    float w = dv * dv;
    float4 x = ((const float4*)X)[i];
    float4 b = ((const float4*)bias)[k4];
    float4 o;
    o.x = b.x + w * x.x; o.y = b.y + w * x.y;
    o.z = b.z + w * x.z; o.w = b.w + w * x.w;
    ((float4*)Out)[i] = o;
}

__global__ void k_scatter(const float* __restrict__ X, float* __restrict__ Out) {
    int e = (blockIdx.x * blockDim.x + threadIdx.x) >> 5;
    if (e >= NE_TOT) return;
    float w = g_enorm[e];
    if (w == 0.f) return;
    int lane = threadIdx.x & 31;
    int s = g_esrc[e], d = g_edst[e];
    const float4* xr = (const float4*)(X + (size_t)s * 256);
    float4 a = xr[lane * 2], b = xr[lane * 2 + 1];
    float* o = Out + (size_t)d * 256 + lane * 8;
    atomicAdd(o + 0, w * a.x); atomicAdd(o + 1, w * a.y);
    atomicAdd(o + 2, w * a.z); atomicAdd(o + 3, w * a.w);
    atomicAdd(o + 4, w * b.x); atomicAdd(o + 5, w * b.y);
    atomicAdd(o + 6, w * b.z); atomicAdd(o + 7, w * b.w);
}

// logits = relu(X_row) @ W(256x64) + bias, class = first-argmax over 64
__global__ void k_logits(const float* __restrict__ X, const float* __restrict__ W,
                         const float* __restrict__ bias) {
    extern __shared__ float sm[];
    float* Ws = sm;               // 16384 floats
    float* rbufs = sm + 16384;    // 8 * 256 floats
    int tid = threadIdx.x;
    for (int i = tid; i < 16384; i += 256) Ws[i] = W[i];
    __syncthreads();
    int warp = tid >> 5, lane = tid & 31;
    float* rbuf = rbufs + warp * 256;
    for (int row = blockIdx.x * 8 + warp; row < N_TOT; row += gridDim.x * 8) {
        const float4* xr = (const float4*)(X + (size_t)row * 256);
        float4 a = xr[lane * 2], b = xr[lane * 2 + 1];
        a.x = fmaxf(a.x, 0.f); a.y = fmaxf(a.y, 0.f); a.z = fmaxf(a.z, 0.f); a.w = fmaxf(a.w, 0.f);
        b.x = fmaxf(b.x, 0.f); b.y = fmaxf(b.y, 0.f); b.z = fmaxf(b.z, 0.f); b.w = fmaxf(b.w, 0.f);
        ((float4*)rbuf)[lane * 2] = a;
        ((float4*)rbuf)[lane * 2 + 1] = b;
        __syncwarp();
        float s0 = bias[lane], s1 = bias[lane + 32];
#pragma unroll 8
        for (int d2 = 0; d2 < 256; d2++) {
            float x = rbuf[d2];
            s0 = fmaf(x, Ws[d2 * 64 + lane], s0);
            s1 = fmaf(x, Ws[d2 * 64 + lane + 32], s1);
        }
        float v = s0; int idx = lane;
        if (s1 > v) { v = s1; idx = lane + 32; }
#pragma unroll
        for (int o = 16; o; o >>= 1) {
            float ov = __shfl_xor_sync(0xffffffffu, v, o);
            int oi = __shfl_xor_sync(0xffffffffu, idx, o);
            if (ov > v || (ov == v && oi < idx)) { v = ov; idx = oi; }
        }
        if (lane == 0) g_cls[row] = idx;
        __syncwarp();
    }
}

__global__ void k_H(float* __restrict__ Hout) {
    int n = blockIdx.x * blockDim.x + threadIdx.x;
    if (n >= N_NODES) return;
    int c0 = g_cls[n];
    int c1 = g_cls[N_NODES + n];
    int c2 = g_cls[2 * N_NODES + n];
    int c3 = g_cls[3 * N_NODES + n];
    int c4 = g_cls[4 * N_NODES + n];
    float* o = Hout + (size_t)n * 64;
#pragma unroll
    for (int j = 0; j < 64; j++)
        o[j] = (float)((c0 == j) + (c1 == j) + (c2 == j) + (c3 == j) + (c4 == j));
}

// hf[c,:] += af2[n,:] for each node n with H[n,c] > 0 (base replica rows only)
__global__ void k_hyperedge(const float* __restrict__ Hout, float* __restrict__ hf) {
    extern __shared__ float acc[];   // 16384 floats
    int tid = threadIdx.x;
    for (int i = tid; i < 16384; i += 256) acc[i] = 0.f;
    __syncthreads();
    int warp = tid >> 5, lane = tid & 31;
    for (int n = blockIdx.x * 8 + warp; n < N_NODES; n += gridDim.x * 8) {
        float h0 = Hout[(size_t)n * 64 + lane];
        float h1 = Hout[(size_t)n * 64 + lane + 32];
        unsigned m0 = __ballot_sync(0xffffffffu, h0 > 0.f);
        unsigned m1 = __ballot_sync(0xffffffffu, h1 > 0.f);
        const float4* xr = (const float4*)(g_B + (size_t)n * 256);
        float4 a = xr[lane * 2], b = xr[lane * 2 + 1];
        unsigned mm = m0;
        while (mm) {
            int c = __ffs(mm) - 1; mm &= mm - 1;
            float* p = acc + c * 256 + lane * 8;
            atomicAdd(p + 0, a.x); atomicAdd(p + 1, a.y); atomicAdd(p + 2, a.z); atomicAdd(p + 3, a.w);
            atomicAdd(p + 4, b.x); atomicAdd(p + 5, b.y); atomicAdd(p + 6, b.z); atomicAdd(p + 7, b.w);
        }
        mm = m1;
        while (mm) {
            int c = (__ffs(mm) - 1) + 32; mm &= mm - 1;
            float* p = acc + c * 256 + lane * 8;
            atomicAdd(p + 0, a.x); atomicAdd(p + 1, a.y); atomicAdd(p + 2, a.z); atomicAdd(p + 3, a.w);
            atomicAdd(p + 4, b.x); atomicAdd(p + 5, b.y); atomicAdd(p + 6, b.z); atomicAdd(p + 7, b.w);
        }
    }
    __syncthreads();
    for (int i = tid; i < 16384; i += 256) atomicAdd(&hf[i], acc[i]);
}

// dots[row, c] = (AF_row . hf[c,:]) * 1/16
__global__ void k_dots(const float* __restrict__ hf, float* __restrict__ out) {
    extern __shared__ float sm[];
    float* Ws = sm;               // Ws[d*64+c] = hf[c*256+d]
    float* rbufs = sm + 16384;
    int tid = threadIdx.x;
    for (int i = tid; i < 16384; i += 256) {
        int c = i >> 8, d2 = i & 255;
        Ws[d2 * 64 + c] = hf[i];
    }
    __syncthreads();
    int warp = tid >> 5, lane = tid & 31;
    float* rbuf = rbufs + warp * 256;
    for (int row = blockIdx.x * 8 + warp; row < N_TOT; row += gridDim.x * 8) {
        const float4* xr = (const float4*)(g_AF + (size_t)row * 256);
        ((float4*)rbuf)[lane * 2] = xr[lane * 2];
        ((float4*)rbuf)[lane * 2 + 1] = xr[lane * 2 + 1];
        __syncwarp();
        float s0 = 0.f, s1 = 0.f;
#pragma unroll 8
        for (int d2 = 0; d2 < 256; d2++) {
            float x = rbuf[d2];
            s0 = fmaf(x, Ws[d2 * 64 + lane], s0);
            s1 = fmaf(x, Ws[d2 * 64 + lane + 32], s1);
        }
        out[(size_t)row * 64 + lane] = s0 * 0.0625f;
        out[(size_t)row * 64 + lane + 32] = s1 * 0.0625f;
        __syncwarp();
    }
}

// ---------------- launch ----------------
extern "C" void kernel_launch(void* const* d_in, const int* in_sizes, int n_in,
                              void* d_out, int out_size) {
    const int*   ei       = (const int*)d_in[0];
    const float* features = (const float*)d_in[1];
    const float* lin_w    = (const float*)d_in[2];
    const float* lin_b    = (const float*)d_in[3];
    const float* gcn0_w   = (const float*)d_in[4];
    const float* gcn0_b   = (const float*)d_in[5];
    const float* gcn1_w   = (const float*)d_in[6];
    const float* gcn1_b   = (const float*)d_in[7];
    const float* lin1_w   = (const float*)d_in[8];
    const float* lin1_b   = (const float*)d_in[9];

    float* out      = (float*)d_out;
    float* H_out    = out;                               // 50000*64
    float* hf_out   = out + (size_t)N_NODES * NS;        // +3,200,000
    float* dots_out = hf_out + NS * D;                   // +16,384

    float *AF, *X, *B, *ZB;
    cudaGetSymbolAddress((void**)&AF, g_AF);
    cudaGetSymbolAddress((void**)&X,  g_X);
    cudaGetSymbolAddress((void**)&B,  g_B);
    cudaGetSymbolAddress((void**)&ZB, g_zerobias);

    cudaFuncSetAttribute(k_logits,    cudaFuncAttributeMaxDynamicSharedMemorySize, 73728);
    cudaFuncSetAttribute(k_dots,      cudaFuncAttributeMaxDynamicSharedMemorySize, 73728);
    cudaFuncSetAttribute(k_hyperedge, cudaFuncAttributeMaxDynamicSharedMemorySize, 65536);

    // 1. assemble all_features
    k_copy_features<<<(N_NODES * D / 4 + 255) / 256, 256>>>((const float4*)features);
    dim3 gN(2, (N_NODES + 127) / 128);
    for (int t = 0; t < T_REP; t++)
        k_sgemm<0><<<gN, 256>>>(features, lin_w + t * 65536, lin_b + t * 256,
                                AF + (size_t)(t + 1) * N_NODES * 256, N_NODES);

    // 2. inverse norms of transformed rows + per-edge best replica
    k_invnorm<<<(T_REP * N_NODES * 32 + 255) / 256, 256>>>();
    k_edge_sim<<<(N_EDGES + 7) / 8, 256>>>(ei);

    // 3. graph build: degrees + per-edge norms
    k_deg_init<<<(N_TOT + 255) / 256, 256>>>();
    k_build_edges<<<(NE_TOT + 255) / 256, 256>>>(ei);
    k_dinv<<<(N_TOT + 255) / 256, 256>>>();
    k_enorm<<<(NE_TOT + 255) / 256, 256>>>();

    // 4. GCN layer 0: X = relu(AF) @ W0 ; B = b0 + dinv^2*X + scatter(norm * X[src])
    dim3 gT(2, (N_TOT + 127) / 128);
    k_sgemm<1><<<gT, 256>>>(AF, gcn0_w, ZB, X, N_TOT);
    k_gcn_init<<<(N_TOT * 64 + 255) / 256, 256>>>(X, gcn0_b, B);
    k_scatter<<<(NE_TOT + 7) / 8, 256>>>(X, B);

    // 5. GCN layer 1: X = relu(B) @ W1 ; B = b1 + dinv^2*X + scatter  (B becomes af2)
    k_sgemm<1><<<gT, 256>>>(B, gcn1_w, ZB, X, N_TOT);
    k_gcn_init<<<(N_TOT * 64 + 255) / 256, 256>>>(X, gcn1_b, B);
    k_scatter<<<(NE_TOT + 7) / 8, 256>>>(X, B);

    // 6. logits -> classes -> H
    k_logits<<<2048, 256, 73728>>>(B, lin1_w, lin1_b);
    k_H<<<(N_NODES + 255) / 256, 256>>>(H_out);

    // 7. hyperedge features (mask^T @ af2[:N])
    cudaMemsetAsync(hf_out, 0, (size_t)NS * D * sizeof(float));
    k_hyperedge<<<160, 256, 65536>>>(H_out, hf_out);

    // 8. dots = all_features @ hf^T * d^-0.5
    k_dots<<<2048, 256, 73728>>>(hf_out, dots_out);
}

// round 2
// speedup vs baseline: 2.0695x; 2.0695x over previous
#include <cuda_runtime.h>

#define N_NODES 50000
#define N_EDGES 800000
#define D 256
#define T_REP 4
#define NS 64
#define N_TOT (5 * N_NODES)                 /* 250000 */
#define NE_TOT (2 * N_EDGES + 3 * N_NODES)  /* 1750000 */
#define SCAN_BLK 1024
#define N_SCAN_BLOCKS ((N_TOT + SCAN_BLK - 1) / SCAN_BLK)  /* 245 */

// ---------------- scratch (device globals; no allocation) ----------------
__device__ float g_AF[(size_t)N_TOT * D];   // all_features
__device__ float g_X[(size_t)N_TOT * D];    // xw scratch
__device__ float g_B[(size_t)N_TOT * D];    // gcn output scratch (h1, then af2)
__device__ float g_invn[T_REP * N_NODES];
__device__ int   g_deg[N_TOT];
__device__ float g_dinv[N_TOT];
__device__ int   g_best[N_EDGES];
__device__ int   g_cls[N_TOT];
__device__ float g_zerobias[D];
// CSR
__device__ int   g_rowptr[N_TOT];
__device__ int   g_blocksum[256];
__device__ int   g_cursor[N_TOT];
__device__ int   g_csr_src[NE_TOT];
__device__ float g_csr_w[NE_TOT];

// ---------------- kernels ----------------

__global__ void k_copy_features(const float4* __restrict__ f) {
    int i = blockIdx.x * blockDim.x + threadIdx.x;
    if (i < N_NODES * D / 4) ((float4*)g_AF)[i] = f[i];
}

// C[M,256] = op(A[M,256]) @ W[256,256] + bias; double-buffered 128x128 tile
template<int RELU>
__global__ __launch_bounds__(256, 2) void k_sgemm(const float* __restrict__ A,
                                                  const float* __restrict__ W,
                                                  const float* __restrict__ bias,
                                                  float* __restrict__ C, int M) {
    __shared__ float As[2][8][132];
    __shared__ float Bs[2][8][132];
    const int tid = threadIdx.x;
    const int tx = tid & 15, ty = tid >> 4;
    const int rowBase = blockIdx.y << 7;
    const int colBase = blockIdx.x << 7;

    const int la_r = tid >> 1;
    const int la_k = (tid & 1) << 2;
    const int lb_k = tid >> 5;
    const int lb_c = (tid & 31) << 2;
    const int ar = rowBase + la_r;
    const bool aok = ar < M;
    const float* Aptr = A + (size_t)ar * 256 + la_k;
    const float* Wptr = W + (size_t)lb_k * 256 + colBase + lb_c;

    float acc[8][8];
#pragma unroll
    for (int i = 0; i < 8; i++)
#pragma unroll
        for (int j = 0; j < 8; j++) acc[i][j] = 0.f;

    float4 na = make_float4(0.f, 0.f, 0.f, 0.f);
    if (aok) na = *(const float4*)Aptr;
    if (RELU) {
        na.x = fmaxf(na.x, 0.f); na.y = fmaxf(na.y, 0.f);
        na.z = fmaxf(na.z, 0.f); na.w = fmaxf(na.w, 0.f);
    }
    float4 nb = *(const float4*)Wptr;
    As[0][la_k + 0][la_r] = na.x; As[0][la_k + 1][la_r] = na.y;
    As[0][la_k + 2][la_r] = na.z; As[0][la_k + 3][la_r] = na.w;
    *(float4*)&Bs[0][lb_k][lb_c] = nb;
    __syncthreads();

#pragma unroll 1
    for (int it = 0; it < 32; ++it) {
        const int cur = it & 1;
        if (it < 31) {
            const int k0 = (it + 1) << 3;
            na = make_float4(0.f, 0.f, 0.f, 0.f);
            if (aok) na = *(const float4*)(Aptr + k0);
            if (RELU) {
                na.x = fmaxf(na.x, 0.f); na.y = fmaxf(na.y, 0.f);
                na.z = fmaxf(na.z, 0.f); na.w = fmaxf(na.w, 0.f);
            }
            nb = *(const float4*)(Wptr + (size_t)k0 * 256);
        }
#pragma unroll
        for (int k = 0; k < 8; k++) {
            float4 a0 = *(const float4*)&As[cur][k][ty * 4];
            float4 a1 = *(const float4*)&As[cur][k][64 + ty * 4];
            float4 b0 = *(const float4*)&Bs[cur][k][tx * 4];
            float4 b1 = *(const float4*)&Bs[cur][k][64 + tx * 4];
            float av[8] = {a0.x, a0.y, a0.z, a0.w, a1.x, a1.y, a1.z, a1.w};
            float bv[8] = {b0.x, b0.y, b0.z, b0.w, b1.x, b1.y, b1.z, b1.w};
#pragma unroll
            for (int i = 0; i < 8; i++)
#pragma unroll
                for (int j = 0; j < 8; j++) acc[i][j] = fmaf(av[i], bv[j], acc[i][j]);
        }
        if (it < 31) {
            const int nxt = cur ^ 1;
            As[nxt][la_k + 0][la_r] = na.x; As[nxt][la_k + 1][la_r] = na.y;
            As[nxt][la_k + 2][la_r] = na.z; As[nxt][la_k + 3][la_r] = na.w;
            *(float4*)&Bs[nxt][lb_k][lb_c] = nb;
        }
        __syncthreads();
    }

#pragma unroll
    for (int i = 0; i < 8; i++) {
        const int r = rowBase + ((i < 4) ? (ty * 4 + i) : (64 + ty * 4 + i - 4));
        if (r >= M) continue;
        const int cb = colBase + tx * 4;
        float4 bb0 = *(const float4*)&bias[cb];
        float4 bb1 = *(const float4*)&bias[cb + 64];
        float4 o0 = make_float4(acc[i][0] + bb0.x, acc[i][1] + bb0.y,
                                acc[i][2] + bb0.z, acc[i][3] + bb0.w);
        float4 o1 = make_float4(acc[i][4] + bb1.x, acc[i][5] + bb1.y,
                                acc[i][6] + bb1.z, acc[i][7] + bb1.w);
        *(float4*)&C[(size_t)r * 256 + cb] = o0;
        *(float4*)&C[(size_t)r * 256 + cb + 64] = o1;
    }
}

__global__ void k_invnorm() {
    int warp = (blockIdx.x * blockDim.x + threadIdx.x) >> 5;
    int lane = threadIdx.x & 31;
    if (warp >= T_REP * N_NODES) return;
    const float4* r = (const float4*)(g_AF + ((size_t)N_NODES + warp) * 256);
    float4 a = r[lane * 2], b = r[lane * 2 + 1];
    float s = a.x * a.x + a.y * a.y + a.z * a.z + a.w * a.w +
              b.x * b.x + b.y * b.y + b.z * b.z + b.w * b.w;
#pragma unroll
    for (int o = 16; o; o >>= 1) s += __shfl_xor_sync(0xffffffffu, s, o);
    if (lane == 0) g_invn[warp] = 1.f / fmaxf(sqrtf(s), 1e-8f);
}

__device__ __forceinline__ float dot8(float4 f0, float4 f1, float4 a, float4 b) {
    return f0.x * a.x + f0.y * a.y + f0.z * a.z + f0.w * a.w +
           f1.x * b.x + f1.y * b.y + f1.z * b.z + f1.w * b.w;
}

// per-edge argmax over t of dot(f[src], transformed_t[dst]) * invn
__global__ void k_edge_sim(const int* __restrict__ ei) {
    int e = (blockIdx.x * blockDim.x + threadIdx.x) >> 5;
    if (e >= N_EDGES) return;
    int lane = threadIdx.x & 31;
    int s = ei[e], d = ei[N_EDGES + e];
    const float4* fr = (const float4*)(g_AF + (size_t)s * 256);
    const float4* t0 = (const float4*)(g_AF + ((size_t)1 * N_NODES + d) * 256);
    const float4* t1 = (const float4*)(g_AF + ((size_t)2 * N_NODES + d) * 256);
    const float4* t2 = (const float4*)(g_AF + ((size_t)3 * N_NODES + d) * 256);
    const float4* t3 = (const float4*)(g_AF + ((size_t)4 * N_NODES + d) * 256);
    float4 f0 = fr[lane * 2], f1 = fr[lane * 2 + 1];
    float4 a0 = t0[lane * 2], b0 = t0[lane * 2 + 1];
    float4 a1 = t1[lane * 2], b1 = t1[lane * 2 + 1];
    float4 a2 = t2[lane * 2], b2 = t2[lane * 2 + 1];
    float4 a3 = t3[lane * 2], b3 = t3[lane * 2 + 1];
    float p0 = dot8(f0, f1, a0, b0);
    float p1 = dot8(f0, f1, a1, b1);
    float p2 = dot8(f0, f1, a2, b2);
    float p3 = dot8(f0, f1, a3, b3);
#pragma unroll
    for (int o = 16; o; o >>= 1) {
        p0 += __shfl_xor_sync(0xffffffffu, p0, o);
        p1 += __shfl_xor_sync(0xffffffffu, p1, o);
        p2 += __shfl_xor_sync(0xffffffffu, p2, o);
        p3 += __shfl_xor_sync(0xffffffffu, p3, o);
    }
    float s0 = p0 * g_invn[d];
    float s1 = p1 * g_invn[N_NODES + d];
    float s2 = p2 * g_invn[2 * N_NODES + d];
    float s3 = p3 * g_invn[3 * N_NODES + d];
    float bv = s0; int bi = 0;
    if (s1 > bv) { bv = s1; bi = 1; }
    if (s2 > bv) { bv = s2; bi = 2; }
    if (s3 > bv) { bv = s3; bi = 3; }
    if (lane == 0) g_best[e] = bi;
}

__global__ void k_deg_init() {
    int i = blockIdx.x * blockDim.x + threadIdx.x;
    if (i < N_TOT) g_deg[i] = 1;   // self loop
}

__device__ __forceinline__ void decode_edge(const int* __restrict__ ei, int i, int& s, int& d) {
    if (i < N_EDGES) {
        s = ei[i]; d = ei[N_EDGES + i];
    } else if (i < 2 * N_EDGES) {
        int e = i - N_EDGES;
        s = ei[e]; d = ei[N_EDGES + e] + g_best[e] * N_NODES;
    } else {
        int r = i - 2 * N_EDGES;
        int rep = r / N_NODES + 1;            // 1..3
        int n = r - (rep - 1) * N_NODES;
        s = n; d = n + rep * N_NODES;
    }
}

__global__ void k_count(const int* __restrict__ ei) {
    int i = blockIdx.x * blockDim.x + threadIdx.x;
    if (i >= NE_TOT) return;
    int s, d;
    decode_edge(ei, i, s, d);
    if (s != d) atomicAdd(&g_deg[d], 1);
}

__global__ void k_dinv() {
    int i = blockIdx.x * blockDim.x + threadIdx.x;
    if (i < N_TOT) g_dinv[i] = rsqrtf((float)g_deg[i]);
}

// ---- exclusive scan of (deg-1) into g_rowptr ----
__global__ void k_scan1() {
    __shared__ int sm[256];
    int tid = threadIdx.x;
    int base = blockIdx.x * SCAN_BLK;
    int loc[4]; int sum = 0;
#pragma unroll
    for (int u = 0; u < 4; u++) {
        int i = base + tid * 4 + u;
        int v = (i < N_TOT) ? (g_deg[i] - 1) : 0;
        loc[u] = sum; sum += v;
    }
    sm[tid] = sum;
    __syncthreads();
    for (int o = 1; o < 256; o <<= 1) {
        int t = (tid >= o) ? sm[tid - o] : 0;
        __syncthreads();
        sm[tid] += t;
        __syncthreads();
    }
    int pre = tid ? sm[tid - 1] : 0;
#pragma unroll
    for (int u = 0; u < 4; u++) {
        int i = base + tid * 4 + u;
        if (i < N_TOT) g_rowptr[i] = pre + loc[u];
    }
    if (tid == 255) g_blocksum[blockIdx.x] = sm[255];
}

__global__ void k_scan2(int nb) {
    __shared__ int sm[256];
    int tid = threadIdx.x;
    sm[tid] = (tid < nb) ? g_blocksum[tid] : 0;
    __syncthreads();
    for (int o = 1; o < 256; o <<= 1) {
        int t = (tid >= o) ? sm[tid - o] : 0;
        __syncthreads();
        sm[tid] += t;
        __syncthreads();
    }
    if (tid < nb) g_blocksum[tid] = tid ? sm[tid - 1] : 0;
}

__global__ void k_scan3() {
    int i = blockIdx.x * blockDim.x + threadIdx.x;
    if (i < N_TOT) g_rowptr[i] += g_blocksum[i >> 10];
}

__global__ void k_fill(const int* __restrict__ ei) {
    int i = blockIdx.x * blockDim.x + threadIdx.x;
    if (i >= NE_TOT) return;
    int s, d;
    decode_edge(ei, i, s, d);
    if (s == d) return;
    int pos = g_rowptr[d] + atomicAdd(&g_cursor[d], 1);
    g_csr_src[pos] = s;
    g_csr_w[pos] = g_dinv[s] * g_dinv[d];
}

// Out[d] = bias + dinv[d]^2*X[d] + sum_{edges into d} w*X[src]; one warp per row
__global__ void k_aggregate(const float* __restrict__ X, const float* __restrict__ bias,
                            float* __restrict__ Out) {
    int w = (blockIdx.x * blockDim.x + threadIdx.x) >> 5;
    if (w >= N_TOT) return;
    int lane = threadIdx.x & 31;
    int start = g_rowptr[w];
    int len = g_deg[w] - 1;
    float dv = g_dinv[w];
    float ws = dv * dv;
    const float4* xd = (const float4*)(X + (size_t)w * 256);
    float4 sa = xd[lane * 2], sb = xd[lane * 2 + 1];
    float acc0 = ws * sa.x, acc1 = ws * sa.y, acc2 = ws * sa.z, acc3 = ws * sa.w;
    float acc4 = ws * sb.x, acc5 = ws * sb.y, acc6 = ws * sb.z, acc7 = ws * sb.w;
    int j = 0;
    for (; j + 2 <= len; j += 2) {
        int s0 = g_csr_src[start + j];
        int s1 = g_csr_src[start + j + 1];
        float w0 = g_csr_w[start + j];
        float w1 = g_csr_w[start + j + 1];
        const float4* x0 = (const float4*)(X + (size_t)s0 * 256);
        const float4* x1 = (const float4*)(X + (size_t)s1 * 256);
        float4 u0 = x0[lane * 2], v0 = x0[lane * 2 + 1];
        float4 u1 = x1[lane * 2], v1 = x1[lane * 2 + 1];
        acc0 = fmaf(w0, u0.x, acc0); acc1 = fmaf(w0, u0.y, acc1);
        acc2 = fmaf(w0, u0.z, acc2); acc3 = fmaf(w0, u0.w, acc3);
        acc4 = fmaf(w0, v0.x, acc4); acc5 = fmaf(w0, v0.y, acc5);
        acc6 = fmaf(w0, v0.z, acc6); acc7 = fmaf(w0, v0.w, acc7);
        acc0 = fmaf(w1, u1.x, acc0); acc1 = fmaf(w1, u1.y, acc1);
        acc2 = fmaf(w1, u1.z, acc2); acc3 = fmaf(w1, u1.w, acc3);
        acc4 = fmaf(w1, v1.x, acc4); acc5 = fmaf(w1, v1.y, acc5);
        acc6 = fmaf(w1, v1.z, acc6); acc7 = fmaf(w1, v1.w, acc7);
    }
    if (j < len) {
        int s0 = g_csr_src[start + j];
        float w0 = g_csr_w[start + j];
        const float4* x0 = (const float4*)(X + (size_t)s0 * 256);
        float4 u0 = x0[lane * 2], v0 = x0[lane * 2 + 1];
        acc0 = fmaf(w0, u0.x, acc0); acc1 = fmaf(w0, u0.y, acc1);
        acc2 = fmaf(w0, u0.z, acc2); acc3 = fmaf(w0, u0.w, acc3);
        acc4 = fmaf(w0, v0.x, acc4); acc5 = fmaf(w0, v0.y, acc5);
        acc6 = fmaf(w0, v0.z, acc6); acc7 = fmaf(w0, v0.w, acc7);
    }
    const float4* b4 = (const float4*)bias;
    float4 bb0 = b4[lane * 2], bb1 = b4[lane * 2 + 1];
    float4 o0 = make_float4(acc0 + bb0.x, acc1 + bb0.y, acc2 + bb0.z, acc3 + bb0.w);
    float4 o1 = make_float4(acc4 + bb1.x, acc5 + bb1.y, acc6 + bb1.z, acc7 + bb1.w);
    float4* od = (float4*)(Out + (size_t)w * 256);
    od[lane * 2] = o0;
    od[lane * 2 + 1] = o1;
}

// logits = relu(X_row) @ W(256x64) + bias, class = first-argmax over 64
__global__ void k_logits(const float* __restrict__ X, const float* __restrict__ W,
                         const float* __restrict__ bias) {
    extern __shared__ float sm[];
    float* Ws = sm;               // 16384 floats
    float* rbufs = sm + 16384;    // 8 * 256 floats
    int tid = threadIdx.x;
    for (int i = tid; i < 16384; i += 256) Ws[i] = W[i];
    __syncthreads();
    int warp = tid >> 5, lane = tid & 31;
    float* rbuf = rbufs + warp * 256;
    for (int row = blockIdx.x * 8 + warp; row < N_TOT; row += gridDim.x * 8) {
        const float4* xr = (const float4*)(X + (size_t)row * 256);
        float4 a = xr[lane * 2], b = xr[lane * 2 + 1];
        a.x = fmaxf(a.x, 0.f); a.y = fmaxf(a.y, 0.f); a.z = fmaxf(a.z, 0.f); a.w = fmaxf(a.w, 0.f);
        b.x = fmaxf(b.x, 0.f); b.y = fmaxf(b.y, 0.f); b.z = fmaxf(b.z, 0.f); b.w = fmaxf(b.w, 0.f);
        ((float4*)rbuf)[lane * 2] = a;
        ((float4*)rbuf)[lane * 2 + 1] = b;
        __syncwarp();
        float s0 = bias[lane], s1 = bias[lane + 32];
#pragma unroll 8
        for (int d2 = 0; d2 < 256; d2++) {
            float x = rbuf[d2];
            s0 = fmaf(x, Ws[d2 * 64 + lane], s0);
            s1 = fmaf(x, Ws[d2 * 64 + lane + 32], s1);
        }
        float v = s0; int idx = lane;
        if (s1 > v) { v = s1; idx = lane + 32; }
#pragma unroll
        for (int o = 16; o; o >>= 1) {
            float ov = __shfl_xor_sync(0xffffffffu, v, o);
            int oi = __shfl_xor_sync(0xffffffffu, idx, o);
            if (ov > v || (ov == v && oi < idx)) { v = ov; idx = oi; }
        }
        if (lane == 0) g_cls[row] = idx;
        __syncwarp();
    }
}

__global__ void k_H(float* __restrict__ Hout) {
    int n = blockIdx.x * blockDim.x + threadIdx.x;
    if (n >= N_NODES) return;
    int c0 = g_cls[n];
    int c1 = g_cls[N_NODES + n];
    int c2 = g_cls[2 * N_NODES + n];
    int c3 = g_cls[3 * N_NODES + n];
    int c4 = g_cls[4 * N_NODES + n];
    float* o = Hout + (size_t)n * 64;
#pragma unroll
    for (int j = 0; j < 64; j++)
        o[j] = (float)((c0 == j) + (c1 == j) + (c2 == j) + (c3 == j) + (c4 == j));
}

// hf[c,:] += af2[n,:] for each node n with H[n,c] > 0
__global__ void k_hyperedge(const float* __restrict__ Hout, float* __restrict__ hf) {
    extern __shared__ float acc[];   // 16384 floats
    int tid = threadIdx.x;
    for (int i = tid; i < 16384; i += 256) acc[i] = 0.f;
    __syncthreads();
    int warp = tid >> 5, lane = tid & 31;
    for (int n = blockIdx.x * 8 + warp; n < N_NODES; n += gridDim.x * 8) {
        float h0 = Hout[(size_t)n * 64 + lane];
        float h1 = Hout[(size_t)n * 64 + lane + 32];
        unsigned m0 = __ballot_sync(0xffffffffu, h0 > 0.f);
        unsigned m1 = __ballot_sync(0xffffffffu, h1 > 0.f);
        const float4* xr = (const float4*)(g_B + (size_t)n * 256);
        float4 a = xr[lane * 2], b = xr[lane * 2 + 1];
        unsigned mm = m0;
        while (mm) {
            int c = __ffs(mm) - 1; mm &= mm - 1;
            float* p = acc + c * 256 + lane * 8;
            atomicAdd(p + 0, a.x); atomicAdd(p + 1, a.y); atomicAdd(p + 2, a.z); atomicAdd(p + 3, a.w);
            atomicAdd(p + 4, b.x); atomicAdd(p + 5, b.y); atomicAdd(p + 6, b.z); atomicAdd(p + 7, b.w);
        }
        mm = m1;
        while (mm) {
            int c = (__ffs(mm) - 1) + 32; mm &= mm - 1;
            float* p = acc + c * 256 + lane * 8;
            atomicAdd(p + 0, a.x); atomicAdd(p + 1, a.y); atomicAdd(p + 2, a.z); atomicAdd(p + 3, a.w);
            atomicAdd(p + 4, b.x); atomicAdd(p + 5, b.y); atomicAdd(p + 6, b.z); atomicAdd(p + 7, b.w);
        }
    }
    __syncthreads();
    for (int i = tid; i < 16384; i += 256) atomicAdd(&hf[i], acc[i]);
}

// dots[row, c] = (AF_row . hf[c,:]) * 1/16
__global__ void k_dots(const float* __restrict__ hf, float* __restrict__ out) {
    extern __shared__ float sm[];
    float* Ws = sm;               // Ws[d*64+c] = hf[c*256+d]
    float* rbufs = sm + 16384;
    int tid = threadIdx.x;
    for (int i = tid; i < 16384; i += 256) {
        int c = i >> 8, d2 = i & 255;
        Ws[d2 * 64 + c] = hf[i];
    }
    __syncthreads();
    int warp = tid >> 5, lane = tid & 31;
    float* rbuf = rbufs + warp * 256;
    for (int row = blockIdx.x * 8 + warp; row < N_TOT; row += gridDim.x * 8) {
        const float4* xr = (const float4*)(g_AF + (size_t)row * 256);
        ((float4*)rbuf)[lane * 2] = xr[lane * 2];
        ((float4*)rbuf)[lane * 2 + 1] = xr[lane * 2 + 1];
        __syncwarp();
        float s0 = 0.f, s1 = 0.f;
#pragma unroll 8
        for (int d2 = 0; d2 < 256; d2++) {
            float x = rbuf[d2];
            s0 = fmaf(x, Ws[d2 * 64 + lane], s0);
            s1 = fmaf(x, Ws[d2 * 64 + lane + 32], s1);
        }
        out[(size_t)row * 64 + lane] = s0 * 0.0625f;
        out[(size_t)row * 64 + lane + 32] = s1 * 0.0625f;
        __syncwarp();
    }
}

// ---------------- launch ----------------
extern "C" void kernel_launch(void* const* d_in, const int* in_sizes, int n_in,
                              void* d_out, int out_size) {
    const int*   ei       = (const int*)d_in[0];
    const float* features = (const float*)d_in[1];
    const float* lin_w    = (const float*)d_in[2];
    const float* lin_b    = (const float*)d_in[3];
    const float* gcn0_w   = (const float*)d_in[4];
    const float* gcn0_b   = (const float*)d_in[5];
    const float* gcn1_w   = (const float*)d_in[6];
    const float* gcn1_b   = (const float*)d_in[7];
    const float* lin1_w   = (const float*)d_in[8];
    const float* lin1_b   = (const float*)d_in[9];

    float* out      = (float*)d_out;
    float* H_out    = out;
    float* hf_out   = out + (size_t)N_NODES * NS;
    float* dots_out = hf_out + NS * D;

    float *AF, *X, *B, *ZB;
    int *CUR;
    cudaGetSymbolAddress((void**)&AF, g_AF);
    cudaGetSymbolAddress((void**)&X,  g_X);
    cudaGetSymbolAddress((void**)&B,  g_B);
    cudaGetSymbolAddress((void**)&ZB, g_zerobias);
    cudaGetSymbolAddress((void**)&CUR, g_cursor);

    cudaFuncSetAttribute(k_logits,    cudaFuncAttributeMaxDynamicSharedMemorySize, 73728);
    cudaFuncSetAttribute(k_dots,      cudaFuncAttributeMaxDynamicSharedMemorySize, 73728);
    cudaFuncSetAttribute(k_hyperedge, cudaFuncAttributeMaxDynamicSharedMemorySize, 65536);

    // 1. assemble all_features
    k_copy_features<<<(N_NODES * D / 4 + 255) / 256, 256>>>((const float4*)features);
    dim3 gN(2, (N_NODES + 127) / 128);
    for (int t = 0; t < T_REP; t++)
        k_sgemm<0><<<gN, 256>>>(features, lin_w + t * 65536, lin_b + t * 256,
                                AF + (size_t)(t + 1) * N_NODES * 256, N_NODES);

    // 2. per-edge best replica
    k_invnorm<<<(T_REP * N_NODES * 32 + 255) / 256, 256>>>();
    k_edge_sim<<<(N_EDGES + 7) / 8, 256>>>(ei);

    // 3. graph build: degrees -> dinv -> CSR (rowptr scan + fill)
    k_deg_init<<<(N_TOT + 255) / 256, 256>>>();
    k_count<<<(NE_TOT + 255) / 256, 256>>>(ei);
    k_dinv<<<(N_TOT + 255) / 256, 256>>>();
    k_scan1<<<N_SCAN_BLOCKS, 256>>>();
    k_scan2<<<1, 256>>>(N_SCAN_BLOCKS);
    k_scan3<<<(N_TOT + 255) / 256, 256>>>();
    cudaMemsetAsync(CUR, 0, N_TOT * sizeof(int));
    k_fill<<<(NE_TOT + 255) / 256, 256>>>(ei);

    // 4. GCN layer 0
    dim3 gT(2, (N_TOT + 127) / 128);
    k_sgemm<1><<<gT, 256>>>(AF, gcn0_w, ZB, X, N_TOT);
    k_aggregate<<<(N_TOT * 32 + 255) / 256, 256>>>(X, gcn0_b, B);

    // 5. GCN layer 1
    k_sgemm<1><<<gT, 256>>>(B, gcn1_w, ZB, X, N_TOT);
    k_aggregate<<<(N_TOT * 32 + 255) / 256, 256>>>(X, gcn1_b, B);

    // 6. logits -> classes -> H
    k_logits<<<2048, 256, 73728>>>(B, lin1_w, lin1_b);
    k_H<<<(N_NODES + 255) / 256, 256>>>(H_out);

    // 7. hyperedge features
    cudaMemsetAsync(hf_out, 0, (size_t)NS * D * sizeof(float));
    k_hyperedge<<<160, 256, 65536>>>(H_out, hf_out);

    // 8. dots
    k_dots<<<2048, 256, 73728>>>(hf_out, dots_out);
}

// round 3
// speedup vs baseline: 2.1472x; 1.0376x over previous
#include <cuda_runtime.h>

#define N_NODES 50000
#define N_EDGES 800000
#define D 256
#define T_REP 4
#define NS 64
#define N_TOT (5 * N_NODES)                 /* 250000 */
#define NE_TOT (2 * N_EDGES + 3 * N_NODES)  /* 1750000 */
#define SCAN_BLK 1024

// ---------------- scratch (device globals; no allocation) ----------------
__device__ float g_AF[(size_t)N_TOT * D];   // all_features
__device__ float g_X[(size_t)N_TOT * D];    // xw scratch
__device__ float g_B[(size_t)N_TOT * D];    // gcn output scratch (h1, then af2)
__device__ float g_invn[T_REP * N_NODES];
__device__ int   g_deg[N_TOT];
__device__ float g_dinv[N_TOT];
__device__ int   g_best[N_EDGES];
__device__ int   g_cls[N_TOT];
__device__ float g_zerobias[D];
// augmented-graph CSR
__device__ int   g_rowptr[N_TOT];
__device__ int   g_blocksum[256];
__device__ int   g_cursor[N_TOT];
__device__ int   g_csr_src[NE_TOT];
__device__ float g_csr_w[NE_TOT];
// original-edge CSR by dst (for edge_sim)
__device__ int   g_odeg[N_NODES];
__device__ int   g_orow[N_NODES];
__device__ int   g_ocur[N_NODES];
__device__ int   g_oedge[N_EDGES];

// ---------------- kernels ----------------

__global__ void k_copy_features(const float4* __restrict__ f) {
    int i = blockIdx.x * blockDim.x + threadIdx.x;
    if (i < N_NODES * D / 4) ((float4*)g_AF)[i] = f[i];
}

// C[M,256] = op(A[M,256]) @ W[256,256] + bias; 128x128 tile, smem + register
// double buffering. blockIdx.z selects weight/bias/output slice (for the 4 heads).
template<int RELU>
__global__ __launch_bounds__(256, 2) void k_sgemm(const float* __restrict__ A,
                                                  const float* __restrict__ W,
                                                  const float* __restrict__ bias,
                                                  float* __restrict__ C, int M,
                                                  int wStride, int cStride) {
    __shared__ float As[2][8][132];
    __shared__ float Bs[2][8][132];
    const int z = blockIdx.z;
    const float* Wz = W + (size_t)z * wStride;
    const float* bz = bias + (size_t)z * (wStride ? 256 : 0);
    float* Cz = C + (size_t)z * cStride;

    const int tid = threadIdx.x;
    const int tx = tid & 15, ty = tid >> 4;
    const int rowBase = blockIdx.y << 7;
    const int colBase = blockIdx.x << 7;

    const int la_r = tid >> 1;
    const int la_k = (tid & 1) << 2;
    const int lb_k = tid >> 5;
    const int lb_c = (tid & 31) << 2;
    const int ar = rowBase + la_r;
    const bool aok = ar < M;
    const float* Aptr = A + (size_t)ar * 256 + la_k;
    const float* Wptr = Wz + (size_t)lb_k * 256 + colBase + lb_c;

    float acc[8][8];
#pragma unroll
    for (int i = 0; i < 8; i++)
#pragma unroll
        for (int j = 0; j < 8; j++) acc[i][j] = 0.f;

    float4 na = make_float4(0.f, 0.f, 0.f, 0.f);
    if (aok) na = *(const float4*)Aptr;
    if (RELU) {
        na.x = fmaxf(na.x, 0.f); na.y = fmaxf(na.y, 0.f);
        na.z = fmaxf(na.z, 0.f); na.w = fmaxf(na.w, 0.f);
    }
    float4 nb = *(const float4*)Wptr;
    As[0][la_k + 0][la_r] = na.x; As[0][la_k + 1][la_r] = na.y;
    As[0][la_k + 2][la_r] = na.z; As[0][la_k + 3][la_r] = na.w;
    *(float4*)&Bs[0][lb_k][lb_c] = nb;
    __syncthreads();

#pragma unroll 1
    for (int it = 0; it < 32; ++it) {
        const int cur = it & 1;
        if (it < 31) {
            const int k0 = (it + 1) << 3;
            na = make_float4(0.f, 0.f, 0.f, 0.f);
            if (aok) na = *(const float4*)(Aptr + k0);
            if (RELU) {
                na.x = fmaxf(na.x, 0.f); na.y = fmaxf(na.y, 0.f);
                na.z = fmaxf(na.z, 0.f); na.w = fmaxf(na.w, 0.f);
            }
            nb = *(const float4*)(Wptr + (size_t)k0 * 256);
        }
        // register-double-buffered fragment loop
        float4 a0c = *(const float4*)&As[cur][0][ty * 4];
        float4 a1c = *(const float4*)&As[cur][0][64 + ty * 4];
        float4 b0c = *(const float4*)&Bs[cur][0][tx * 4];
        float4 b1c = *(const float4*)&Bs[cur][0][64 + tx * 4];
#pragma unroll
        for (int k = 0; k < 8; k++) {
            float4 a0n, a1n, b0n, b1n;
            if (k < 7) {
                a0n = *(const float4*)&As[cur][k + 1][ty * 4];
                a1n = *(const float4*)&As[cur][k + 1][64 + ty * 4];
                b0n = *(const float4*)&Bs[cur][k + 1][tx * 4];
                b1n = *(const float4*)&Bs[cur][k + 1][64 + tx * 4];
            }
            float av[8] = {a0c.x, a0c.y, a0c.z, a0c.w, a1c.x, a1c.y, a1c.z, a1c.w};
            float bv[8] = {b0c.x, b0c.y, b0c.z, b0c.w, b1c.x, b1c.y, b1c.z, b1c.w};
#pragma unroll
            for (int i = 0; i < 8; i++)
#pragma unroll
                for (int j = 0; j < 8; j++) acc[i][j] = fmaf(av[i], bv[j], acc[i][j]);
            if (k < 7) { a0c = a0n; a1c = a1n; b0c = b0n; b1c = b1n; }
        }
        if (it < 31) {
            const int nxt = cur ^ 1;
            As[nxt][la_k + 0][la_r] = na.x; As[nxt][la_k + 1][la_r] = na.y;
            As[nxt][la_k + 2][la_r] = na.z; As[nxt][la_k + 3][la_r] = na.w;
            *(float4*)&Bs[nxt][lb_k][lb_c] = nb;
        }
        __syncthreads();
    }

#pragma unroll
    for (int i = 0; i < 8; i++) {
        const int r = rowBase + ((i < 4) ? (ty * 4 + i) : (64 + ty * 4 + i - 4));
        if (r >= M) continue;
        const int cb = colBase + tx * 4;
        float4 bb0 = *(const float4*)&bz[cb];
        float4 bb1 = *(const float4*)&bz[cb + 64];
        float4 o0 = make_float4(acc[i][0] + bb0.x, acc[i][1] + bb0.y,
                                acc[i][2] + bb0.z, acc[i][3] + bb0.w);
        float4 o1 = make_float4(acc[i][4] + bb1.x, acc[i][5] + bb1.y,
                                acc[i][6] + bb1.z, acc[i][7] + bb1.w);
        *(float4*)&Cz[(size_t)r * 256 + cb] = o0;
        *(float4*)&Cz[(size_t)r * 256 + cb + 64] = o1;
    }
}

__global__ void k_invnorm() {
    int warp = (blockIdx.x * blockDim.x + threadIdx.x) >> 5;
    int lane = threadIdx.x & 31;
    if (warp >= T_REP * N_NODES) return;
    const float4* r = (const float4*)(g_AF + ((size_t)N_NODES + warp) * 256);
    float4 a = r[lane * 2], b = r[lane * 2 + 1];
    float s = a.x * a.x + a.y * a.y + a.z * a.z + a.w * a.w +
              b.x * b.x + b.y * b.y + b.z * b.z + b.w * b.w;
#pragma unroll
    for (int o = 16; o; o >>= 1) s += __shfl_xor_sync(0xffffffffu, s, o);
    if (lane == 0) g_invn[warp] = 1.f / fmaxf(sqrtf(s), 1e-8f);
}

__device__ __forceinline__ float dot8(float4 f0, float4 f1, float4 a, float4 b) {
    return f0.x * a.x + f0.y * a.y + f0.z * a.z + f0.w * a.w +
           f1.x * b.x + f1.y * b.y + f1.z * b.z + f1.w * b.w;
}

// ---- original-edge CSR (group edges by dst) ----
__global__ void k_ocount(const int* __restrict__ ei) {
    int i = blockIdx.x * blockDim.x + threadIdx.x;
    if (i < N_EDGES) atomicAdd(&g_odeg[ei[N_EDGES + i]], 1);
}

__global__ void k_ofill(const int* __restrict__ ei) {
    int i = blockIdx.x * blockDim.x + threadIdx.x;
    if (i >= N_EDGES) return;
    int d = ei[N_EDGES + i];
    int pos = g_orow[d] + atomicAdd(&g_ocur[d], 1);
    g_oedge[pos] = i;
}

// one warp per dst node: load its 4 replica rows once, iterate incoming edges
__global__ void k_edge_sim2(const int* __restrict__ ei) {
    int d = (blockIdx.x * blockDim.x + threadIdx.x) >> 5;
    if (d >= N_NODES) return;
    int lane = threadIdx.x & 31;
    int len = g_odeg[d];
    if (len == 0) return;
    int start = g_orow[d];
    const float4* t0 = (const float4*)(g_AF + ((size_t)1 * N_NODES + d) * 256);
    const float4* t1 = (const float4*)(g_AF + ((size_t)2 * N_NODES + d) * 256);
    const float4* t2 = (const float4*)(g_AF + ((size_t)3 * N_NODES + d) * 256);
    const float4* t3 = (const float4*)(g_AF + ((size_t)4 * N_NODES + d) * 256);
    float4 a0 = t0[lane * 2], b0 = t0[lane * 2 + 1];
    float4 a1 = t1[lane * 2], b1 = t1[lane * 2 + 1];
    float4 a2 = t2[lane * 2], b2 = t2[lane * 2 + 1];
    float4 a3 = t3[lane * 2], b3 = t3[lane * 2 + 1];
    float i0 = g_invn[d];
    float i1 = g_invn[N_NODES + d];
    float i2 = g_invn[2 * N_NODES + d];
    float i3 = g_invn[3 * N_NODES + d];
    for (int j = 0; j < len; j++) {
        int e = g_oedge[start + j];
        int s = ei[e];
        const float4* fr = (const float4*)(g_AF + (size_t)s * 256);
        float4 f0 = fr[lane * 2], f1 = fr[lane * 2 + 1];
        float p0 = dot8(f0, f1, a0, b0);
        float p1 = dot8(f0, f1, a1, b1);
        float p2 = dot8(f0, f1, a2, b2);
        float p3 = dot8(f0, f1, a3, b3);
#pragma unroll
        for (int o = 16; o; o >>= 1) {
            p0 += __shfl_xor_sync(0xffffffffu, p0, o);
            p1 += __shfl_xor_sync(0xffffffffu, p1, o);
            p2 += __shfl_xor_sync(0xffffffffu, p2, o);
            p3 += __shfl_xor_sync(0xffffffffu, p3, o);
        }
        float s0 = p0 * i0, s1 = p1 * i1, s2 = p2 * i2, s3 = p3 * i3;
        float bv = s0; int bi = 0;
        if (s1 > bv) { bv = s1; bi = 1; }
        if (s2 > bv) { bv = s2; bi = 2; }
        if (s3 > bv) { bv = s3; bi = 3; }
        if (lane == 0) g_best[e] = bi;
    }
}

__global__ void k_deg_init() {
    int i = blockIdx.x * blockDim.x + threadIdx.x;
    if (i < N_TOT) g_deg[i] = 1;   // self loop
}

__device__ __forceinline__ void decode_edge(const int* __restrict__ ei, int i, int& s, int& d) {
    if (i < N_EDGES) {
        s = ei[i]; d = ei[N_EDGES + i];
    } else if (i < 2 * N_EDGES) {
        int e = i - N_EDGES;
        s = ei[e]; d = ei[N_EDGES + e] + g_best[e] * N_NODES;
    } else {
        int r = i - 2 * N_EDGES;
        int rep = r / N_NODES + 1;            // 1..3
        int n = r - (rep - 1) * N_NODES;
        s = n; d = n + rep * N_NODES;
    }
}

__global__ void k_count(const int* __restrict__ ei) {
    int i = blockIdx.x * blockDim.x + threadIdx.x;
    if (i >= NE_TOT) return;
    int s, d;
    decode_edge(ei, i, s, d);
    if (s != d) atomicAdd(&g_deg[d], 1);
}

__global__ void k_dinv() {
    int i = blockIdx.x * blockDim.x + threadIdx.x;
    if (i < N_TOT) g_dinv[i] = rsqrtf((float)g_deg[i]);
}

// ---- generic exclusive scan: out = exscan(in - minus) ----
__global__ void k_scan1(const int* __restrict__ in, int* __restrict__ out, int n, int minus) {
    __shared__ int sm[256];
    int tid = threadIdx.x;
    int base = blockIdx.x * SCAN_BLK;
    int loc[4]; int sum = 0;
#pragma unroll
    for (int u = 0; u < 4; u++) {
        int i = base + tid * 4 + u;
        int v = (i < n) ? (in[i] - minus) : 0;
        loc[u] = sum; sum += v;
    }
    sm[tid] = sum;
    __syncthreads();
    for (int o = 1; o < 256; o <<= 1) {
        int t = (tid >= o) ? sm[tid - o] : 0;
        __syncthreads();
        sm[tid] += t;
        __syncthreads();
    }
    int pre = tid ? sm[tid - 1] : 0;
#pragma unroll
    for (int u = 0; u < 4; u++) {
        int i = base + tid * 4 + u;
        if (i < n) out[i] = pre + loc[u];
    }
    if (tid == 255) g_blocksum[blockIdx.x] = sm[255];
}

__global__ void k_scan2(int nb) {
    __shared__ int sm[256];
    int tid = threadIdx.x;
    sm[tid] = (tid < nb) ? g_blocksum[tid] : 0;
    __syncthreads();
    for (int o = 1; o < 256; o <<= 1) {
        int t = (tid >= o) ? sm[tid - o] : 0;
        __syncthreads();
        sm[tid] += t;
        __syncthreads();
    }
    if (tid < nb) g_blocksum[tid] = tid ? sm[tid - 1] : 0;
}

__global__ void k_scan3(int* __restrict__ out, int n) {
    int i = blockIdx.x * blockDim.x + threadIdx.x;
    if (i < n) out[i] += g_blocksum[i >> 10];
}

__global__ void k_fill(const int* __restrict__ ei) {
    int i = blockIdx.x * blockDim.x + threadIdx.x;
    if (i >= NE_TOT) return;
    int s, d;
    decode_edge(ei, i, s, d);
    if (s == d) return;
    int pos = g_rowptr[d] + atomicAdd(&g_cursor[d], 1);
    g_csr_src[pos] = s;
    g_csr_w[pos] = g_dinv[s] * g_dinv[d];
}

// Out[d] = bias + dinv[d]^2*X[d] + sum_{edges into d} w*X[src]; one warp per row
__global__ void k_aggregate(const float* __restrict__ X, const float* __restrict__ bias,
                            float* __restrict__ Out) {
    int w = (blockIdx.x * blockDim.x + threadIdx.x) >> 5;
    if (w >= N_TOT) return;
    int lane = threadIdx.x & 31;
    int start = g_rowptr[w];
    int len = g_deg[w] - 1;
    float dv = g_dinv[w];
    float ws = dv * dv;
    const float4* xd = (const float4*)(X + (size_t)w * 256);
    float4 sa = xd[lane * 2], sb = xd[lane * 2 + 1];
    float acc0 = ws * sa.x, acc1 = ws * sa.y, acc2 = ws * sa.z, acc3 = ws * sa.w;
    float acc4 = ws * sb.x, acc5 = ws * sb.y, acc6 = ws * sb.z, acc7 = ws * sb.w;
    int j = 0;
    for (; j + 2 <= len; j += 2) {
        int s0 = g_csr_src[start + j];
        int s1 = g_csr_src[start + j + 1];
        float w0 = g_csr_w[start + j];
        float w1 = g_csr_w[start + j + 1];
        const float4* x0 = (const float4*)(X + (size_t)s0 * 256);
        const float4* x1 = (const float4*)(X + (size_t)s1 * 256);
        float4 u0 = x0[lane * 2], v0 = x0[lane * 2 + 1];
        float4 u1 = x1[lane * 2], v1 = x1[lane * 2 + 1];
        acc0 = fmaf(w0, u0.x, acc0); acc1 = fmaf(w0, u0.y, acc1);
        acc2 = fmaf(w0, u0.z, acc2); acc3 = fmaf(w0, u0.w, acc3);
        acc4 = fmaf(w0, v0.x, acc4); acc5 = fmaf(w0, v0.y, acc5);
        acc6 = fmaf(w0, v0.z, acc6); acc7 = fmaf(w0, v0.w, acc7);
        acc0 = fmaf(w1, u1.x, acc0); acc1 = fmaf(w1, u1.y, acc1);
        acc2 = fmaf(w1, u1.z, acc2); acc3 = fmaf(w1, u1.w, acc3);
        acc4 = fmaf(w1, v1.x, acc4); acc5 = fmaf(w1, v1.y, acc5);
        acc6 = fmaf(w1, v1.z, acc6); acc7 = fmaf(w1, v1.w, acc7);
    }
    if (j < len) {
        int s0 = g_csr_src[start + j];
        float w0 = g_csr_w[start + j];
        const float4* x0 = (const float4*)(X + (size_t)s0 * 256);
        float4 u0 = x0[lane * 2], v0 = x0[lane * 2 + 1];
        acc0 = fmaf(w0, u0.x, acc0); acc1 = fmaf(w0, u0.y, acc1);
        acc2 = fmaf(w0, u0.z, acc2); acc3 = fmaf(w0, u0.w, acc3);
        acc4 = fmaf(w0, v0.x, acc4); acc5 = fmaf(w0, v0.y, acc5);
        acc6 = fmaf(w0, v0.z, acc6); acc7 = fmaf(w0, v0.w, acc7);
    }
    const float4* b4 = (const float4*)bias;
    float4 bb0 = b4[lane * 2], bb1 = b4[lane * 2 + 1];
    float4 o0 = make_float4(acc0 + bb0.x, acc1 + bb0.y, acc2 + bb0.z, acc3 + bb0.w);
    float4 o1 = make_float4(acc4 + bb1.x, acc5 + bb1.y, acc6 + bb1.z, acc7 + bb1.w);
    float4* od = (float4*)(Out + (size_t)w * 256);
    od[lane * 2] = o0;
    od[lane * 2 + 1] = o1;
}

// logits = relu(X_row) @ W(256x64) + bias, class = first-argmax over 64
__global__ void k_logits(const float* __restrict__ X, const float* __restrict__ W,
                         const float* __restrict__ bias) {
    extern __shared__ float sm[];
    float* Ws = sm;               // 16384 floats
    float* rbufs = sm + 16384;    // 8 * 256 floats
    int tid = threadIdx.x;
    for (int i = tid; i < 16384; i += 256) Ws[i] = W[i];
    __syncthreads();
    int warp = tid >> 5, lane = tid & 31;
    float* rbuf = rbufs + warp * 256;
    for (int row = blockIdx.x * 8 + warp; row < N_TOT; row += gridDim.x * 8) {
        const float4* xr = (const float4*)(X + (size_t)row * 256);
        float4 a = xr[lane * 2], b = xr[lane * 2 + 1];
        a.x = fmaxf(a.x, 0.f); a.y = fmaxf(a.y, 0.f); a.z = fmaxf(a.z, 0.f); a.w = fmaxf(a.w, 0.f);
        b.x = fmaxf(b.x, 0.f); b.y = fmaxf(b.y, 0.f); b.z = fmaxf(b.z, 0.f); b.w = fmaxf(b.w, 0.f);
        ((float4*)rbuf)[lane * 2] = a;
        ((float4*)rbuf)[lane * 2 + 1] = b;
        __syncwarp();
        float s0 = bias[lane], s1 = bias[lane + 32];
#pragma unroll 8
        for (int d2 = 0; d2 < 256; d2++) {
            float x = rbuf[d2];
            s0 = fmaf(x, Ws[d2 * 64 + lane], s0);
            s1 = fmaf(x, Ws[d2 * 64 + lane + 32], s1);
        }
        float v = s0; int idx = lane;
        if (s1 > v) { v = s1; idx = lane + 32; }
#pragma unroll
        for (int o = 16; o; o >>= 1) {
            float ov = __shfl_xor_sync(0xffffffffu, v, o);
            int oi = __shfl_xor_sync(0xffffffffu, idx, o);
            if (ov > v || (ov == v && oi < idx)) { v = ov; idx = oi; }
        }
        if (lane == 0) g_cls[row] = idx;
        __syncwarp();
    }
}

__global__ void k_H(float* __restrict__ Hout) {
    int n = blockIdx.x * blockDim.x + threadIdx.x;
    if (n >= N_NODES) return;
    int c0 = g_cls[n];
    int c1 = g_cls[N_NODES + n];
    int c2 = g_cls[2 * N_NODES + n];
    int c3 = g_cls[3 * N_NODES + n];
    int c4 = g_cls[4 * N_NODES + n];
    float* o = Hout + (size_t)n * 64;
#pragma unroll
    for (int j = 0; j < 64; j++)
        o[j] = (float)((c0 == j) + (c1 == j) + (c2 == j) + (c3 == j) + (c4 == j));
}

// hf[c,:] += af2[n,:] for each node n with H[n,c] > 0
__global__ void k_hyperedge(const float* __restrict__ Hout, float* __restrict__ hf) {
    extern __shared__ float acc[];   // 16384 floats
    int tid = threadIdx.x;
    for (int i = tid; i < 16384; i += 256) acc[i] = 0.f;
    __syncthreads();
    int warp = tid >> 5, lane = tid & 31;
    for (int n = blockIdx.x * 8 + warp; n < N_NODES; n += gridDim.x * 8) {
        float h0 = Hout[(size_t)n * 64 + lane];
        float h1 = Hout[(size_t)n * 64 + lane + 32];
        unsigned m0 = __ballot_sync(0xffffffffu, h0 > 0.f);
        unsigned m1 = __ballot_sync(0xffffffffu, h1 > 0.f);
        const float4* xr = (const float4*)(g_B + (size_t)n * 256);
        float4 a = xr[lane * 2], b = xr[lane * 2 + 1];
        unsigned mm = m0;
        while (mm) {
            int c = __ffs(mm) - 1; mm &= mm - 1;
            float* p = acc + c * 256 + lane * 8;
            atomicAdd(p + 0, a.x); atomicAdd(p + 1, a.y); atomicAdd(p + 2, a.z); atomicAdd(p + 3, a.w);
            atomicAdd(p + 4, b.x); atomicAdd(p + 5, b.y); atomicAdd(p + 6, b.z); atomicAdd(p + 7, b.w);
        }
        mm = m1;
        while (mm) {
            int c = (__ffs(mm) - 1) + 32; mm &= mm - 1;
            float* p = acc + c * 256 + lane * 8;
            atomicAdd(p + 0, a.x); atomicAdd(p + 1, a.y); atomicAdd(p + 2, a.z); atomicAdd(p + 3, a.w);
            atomicAdd(p + 4, b.x); atomicAdd(p + 5, b.y); atomicAdd(p + 6, b.z); atomicAdd(p + 7, b.w);
        }
    }
    __syncthreads();
    for (int i = tid; i < 16384; i += 256) atomicAdd(&hf[i], acc[i]);
}

// dots[row, c] = (AF_row . hf[c,:]) * 1/16
__global__ void k_dots(const float* __restrict__ hf, float* __restrict__ out) {
    extern __shared__ float sm[];
    float* Ws = sm;               // Ws[d*64+c] = hf[c*256+d]
    float* rbufs = sm + 16384;
    int tid = threadIdx.x;
    for (int i = tid; i < 16384; i += 256) {
        int c = i >> 8, d2 = i & 255;
        Ws[d2 * 64 + c] = hf[i];
    }
    __syncthreads();
    int warp = tid >> 5, lane = tid & 31;
    float* rbuf = rbufs + warp * 256;
    for (int row = blockIdx.x * 8 + warp; row < N_TOT; row += gridDim.x * 8) {
        const float4* xr = (const float4*)(g_AF + (size_t)row * 256);
        ((float4*)rbuf)[lane * 2] = xr[lane * 2];
        ((float4*)rbuf)[lane * 2 + 1] = xr[lane * 2 + 1];
        __syncwarp();
        float s0 = 0.f, s1 = 0.f;
#pragma unroll 8
        for (int d2 = 0; d2 < 256; d2++) {
            float x = rbuf[d2];
            s0 = fmaf(x, Ws[d2 * 64 + lane], s0);
            s1 = fmaf(x, Ws[d2 * 64 + lane + 32], s1);
        }
        out[(size_t)row * 64 + lane] = s0 * 0.0625f;
        out[(size_t)row * 64 + lane + 32] = s1 * 0.0625f;
        __syncwarp();
    }
}

// ---------------- launch ----------------
extern "C" void kernel_launch(void* const* d_in, const int* in_sizes, int n_in,
                              void* d_out, int out_size) {
    const int*   ei       = (const int*)d_in[0];
    const float* features = (const float*)d_in[1];
    const float* lin_w    = (const float*)d_in[2];
    const float* lin_b    = (const float*)d_in[3];
    const float* gcn0_w   = (const float*)d_in[4];
    const float* gcn0_b   = (const float*)d_in[5];
    const float* gcn1_w   = (const float*)d_in[6];
    const float* gcn1_b   = (const float*)d_in[7];
    const float* lin1_w   = (const float*)d_in[8];
    const float* lin1_b   = (const float*)d_in[9];

    float* out      = (float*)d_out;
    float* H_out    = out;
    float* hf_out   = out + (size_t)N_NODES * NS;
    float* dots_out = hf_out + NS * D;

    float *AF, *X, *B, *ZB;
    int *CUR, *DEG, *ROWPTR, *ODEG, *OROW, *OCUR;
    cudaGetSymbolAddress((void**)&AF, g_AF);
    cudaGetSymbolAddress((void**)&X,  g_X);
    cudaGetSymbolAddress((void**)&B,  g_B);
    cudaGetSymbolAddress((void**)&ZB, g_zerobias);
    cudaGetSymbolAddress((void**)&CUR, g_cursor);
    cudaGetSymbolAddress((void**)&DEG, g_deg);
    cudaGetSymbolAddress((void**)&ROWPTR, g_rowptr);
    cudaGetSymbolAddress((void**)&ODEG, g_odeg);
    cudaGetSymbolAddress((void**)&OROW, g_orow);
    cudaGetSymbolAddress((void**)&OCUR, g_ocur);

    cudaFuncSetAttribute(k_logits,    cudaFuncAttributeMaxDynamicSharedMemorySize, 73728);
    cudaFuncSetAttribute(k_dots,      cudaFuncAttributeMaxDynamicSharedMemorySize, 73728);
    cudaFuncSetAttribute(k_hyperedge, cudaFuncAttributeMaxDynamicSharedMemorySize, 65536);

    const int nb_tot  = (N_TOT + SCAN_BLK - 1) / SCAN_BLK;     // 245
    const int nb_node = (N_NODES + SCAN_BLK - 1) / SCAN_BLK;   // 49

    // 0. original-edge CSR by dst (independent of GEMMs)
    cudaMemsetAsync(ODEG, 0, N_NODES * sizeof(int));
    cudaMemsetAsync(OCUR, 0, N_NODES * sizeof(int));
    k_ocount<<<(N_EDGES + 255) / 256, 256>>>(ei);
    k_scan1<<<nb_node, 256>>>(ODEG, OROW, N_NODES, 0);
    k_scan2<<<1, 256>>>(nb_node);
    k_scan3<<<(N_NODES + 255) / 256, 256>>>(OROW, N_NODES);
    k_ofill<<<(N_EDGES + 255) / 256, 256>>>(ei);

    // 1. assemble all_features (4 heads in one launch via blockIdx.z)
    k_copy_features<<<(N_NODES * D / 4 + 255) / 256, 256>>>((const float4*)features);
    dim3 gN(2, (N_NODES + 127) / 128, 4);
    k_sgemm<0><<<gN, 256>>>(features, lin_w, lin_b,
                            AF + (size_t)N_NODES * 256, N_NODES,
                            65536, N_NODES * 256);

    // 2. per-edge best replica (dst-grouped)
    k_invnorm<<<(T_REP * N_NODES * 32 + 255) / 256, 256>>>();
    k_edge_sim2<<<(N_NODES * 32 + 255) / 256, 256>>>(ei);

    // 3. augmented-graph degrees -> dinv -> CSR
    k_deg_init<<<(N_TOT + 255) / 256, 256>>>();
    k_count<<<(NE_TOT + 255) / 256, 256>>>(ei);
    k_dinv<<<(N_TOT + 255) / 256, 256>>>();
    k_scan1<<<nb_tot, 256>>>(DEG, ROWPTR, N_TOT, 1);
    k_scan2<<<1, 256>>>(nb_tot);
    k_scan3<<<(N_TOT + 255) / 256, 256>>>(ROWPTR, N_TOT);
    cudaMemsetAsync(CUR, 0, N_TOT * sizeof(int));
    k_fill<<<(NE_TOT + 255) / 256, 256>>>(ei);

    // 4. GCN layer 0
    dim3 gT(2, (N_TOT + 127) / 128, 1);
    k_sgemm<1><<<gT, 256>>>(AF, gcn0_w, ZB, X, N_TOT, 0, 0);
    k_aggregate<<<(N_TOT * 32 + 255) / 256, 256>>>(X, gcn0_b, B);

    // 5. GCN layer 1
    k_sgemm<1><<<gT, 256>>>(B, gcn1_w, ZB, X, N_TOT, 0, 0);
    k_aggregate<<<(N_TOT * 32 + 255) / 256, 256>>>(X, gcn1_b, B);

    // 6. logits -> classes -> H
    k_logits<<<2048, 256, 73728>>>(B, lin1_w, lin1_b);
    k_H<<<(N_NODES + 255) / 256, 256>>>(H_out);

    // 7. hyperedge features
    cudaMemsetAsync(hf_out, 0, (size_t)NS * D * sizeof(float));
    k_hyperedge<<<160, 256, 65536>>>(H_out, hf_out);

    // 8. dots
    k_dots<<<2048, 256, 73728>>>(hf_out, dots_out);
}

// round 4
// speedup vs baseline: 2.2136x; 1.0309x over previous
#include <cuda_runtime.h>

#define N_NODES 50000
#define N_EDGES 800000
#define D 256
#define T_REP 4
#define NS 64
#define N_TOT (5 * N_NODES)                 /* 250000 */
#define NE_TOT (2 * N_EDGES + 3 * N_NODES)  /* 1750000 */
#define SCAN_BLK 1024

typedef unsigned long long u64;

#define FMA2(acc, a, b) asm("fma.rn.f32x2 %0, %1, %2, %0;" : "+l"(acc) : "l"(a), "l"(b))
#define PACK_DUP(out, x) asm("mov.b64 %0, {%1, %1};" : "=l"(out) : "r"(x))
#define PACK2(out, lo, hi) asm("mov.b64 %0, {%1, %2};" : "=l"(out) : "r"(lo), "r"(hi))
#define UNPACK2(lo, hi, v) asm("mov.b64 {%0, %1}, %2;" : "=r"(lo), "=r"(hi) : "l"(v))

// ---------------- scratch (device globals; no allocation) ----------------
__device__ float g_AF[(size_t)N_TOT * D];   // all_features
__device__ float g_X[(size_t)N_TOT * D];    // xw scratch
__device__ float g_B[(size_t)N_TOT * D];    // gcn output scratch (h1, then af2)
__device__ float g_invn[T_REP * N_NODES];
__device__ int   g_deg[N_TOT];
__device__ float g_dinv[N_TOT];
__device__ int   g_best[N_EDGES];
__device__ int   g_cls[N_TOT];
__device__ float g_zerobias[D];
// augmented-graph CSR
__device__ int   g_rowptr[N_TOT];
__device__ int   g_blocksum[256];
__device__ int   g_cursor[N_TOT];
__device__ int   g_csr_src[NE_TOT];
__device__ float g_csr_w[NE_TOT];
// original-edge CSR by dst (for edge_sim)
__device__ int   g_odeg[N_NODES];
__device__ int   g_orow[N_NODES];
__device__ int   g_ocur[N_NODES];
__device__ int   g_oedge[N_EDGES];

// ---------------- kernels ----------------

__global__ void k_copy_features(const float4* __restrict__ f) {
    int i = blockIdx.x * blockDim.x + threadIdx.x;
    if (i < N_NODES * D / 4) ((float4*)g_AF)[i] = f[i];
}

// C[M,256] = op(A[M,256]) @ W[256,256] + bias; 128x128 tile, smem double buffer,
// packed-f32x2 FMA inner loop. blockIdx.z selects head slice.
template<int RELU>
__global__ __launch_bounds__(256, 2) void k_sgemm(const float* __restrict__ A,
                                                  const float* __restrict__ W,
                                                  const float* __restrict__ bias,
                                                  float* __restrict__ C, int M,
                                                  int wStride, int cStride) {
    __shared__ float As[2][8][132];
    __shared__ float Bs[2][8][132];
    const int z = blockIdx.z;
    const float* Wz = W + (size_t)z * wStride;
    const float* bz = bias + (size_t)z * (wStride ? 256 : 0);
    float* Cz = C + (size_t)z * cStride;

    const int tid = threadIdx.x;
    const int tx = tid & 15, ty = tid >> 4;
    const int rowBase = blockIdx.y << 7;
    const int colBase = blockIdx.x << 7;

    const int la_r = tid >> 1;
    const int la_k = (tid & 1) << 2;
    const int lb_k = tid >> 5;
    const int lb_c = (tid & 31) << 2;
    const int ar = rowBase + la_r;
    const bool aok = ar < M;
    const float* Aptr = A + (size_t)ar * 256 + la_k;
    const float* Wptr = Wz + (size_t)lb_k * 256 + colBase + lb_c;

    u64 acc2[8][4];
#pragma unroll
    for (int i = 0; i < 8; i++)
#pragma unroll
        for (int j = 0; j < 4; j++) acc2[i][j] = 0ull;

    float4 na = make_float4(0.f, 0.f, 0.f, 0.f);
    if (aok) na = *(const float4*)Aptr;
    if (RELU) {
        na.x = fmaxf(na.x, 0.f); na.y = fmaxf(na.y, 0.f);
        na.z = fmaxf(na.z, 0.f); na.w = fmaxf(na.w, 0.f);
    }
    float4 nb = *(const float4*)Wptr;
    As[0][la_k + 0][la_r] = na.x; As[0][la_k + 1][la_r] = na.y;
    As[0][la_k + 2][la_r] = na.z; As[0][la_k + 3][la_r] = na.w;
    *(float4*)&Bs[0][lb_k][lb_c] = nb;
    __syncthreads();

#pragma unroll 1
    for (int it = 0; it < 32; ++it) {
        const int cur = it & 1;
        if (it < 31) {
            const int k0 = (it + 1) << 3;
            na = make_float4(0.f, 0.f, 0.f, 0.f);
            if (aok) na = *(const float4*)(Aptr + k0);
            if (RELU) {
                na.x = fmaxf(na.x, 0.f); na.y = fmaxf(na.y, 0.f);
                na.z = fmaxf(na.z, 0.f); na.w = fmaxf(na.w, 0.f);
            }
            nb = *(const float4*)(Wptr + (size_t)k0 * 256);
        }
#pragma unroll
        for (int k = 0; k < 8; k++) {
            float4 a0 = *(const float4*)&As[cur][k][ty * 4];
            float4 a1 = *(const float4*)&As[cur][k][64 + ty * 4];
            ulonglong2 b0 = *(const ulonglong2*)&Bs[cur][k][tx * 4];
            ulonglong2 b1 = *(const ulonglong2*)&Bs[cur][k][64 + tx * 4];
            float av[8] = {a0.x, a0.y, a0.z, a0.w, a1.x, a1.y, a1.z, a1.w};
#pragma unroll
            for (int i = 0; i < 8; i++) {
                u64 ap;
                PACK_DUP(ap, __float_as_uint(av[i]));
                FMA2(acc2[i][0], ap, b0.x);
                FMA2(acc2[i][1], ap, b0.y);
                FMA2(acc2[i][2], ap, b1.x);
                FMA2(acc2[i][3], ap, b1.y);
            }
        }
        if (it < 31) {
            const int nxt = cur ^ 1;
            As[nxt][la_k + 0][la_r] = na.x; As[nxt][la_k + 1][la_r] = na.y;
            As[nxt][la_k + 2][la_r] = na.z; As[nxt][la_k + 3][la_r] = na.w;
            *(float4*)&Bs[nxt][lb_k][lb_c] = nb;
        }
        __syncthreads();
    }

#pragma unroll
    for (int i = 0; i < 8; i++) {
        const int r = rowBase + ((i < 4) ? (ty * 4 + i) : (64 + ty * 4 + i - 4));
        if (r >= M) continue;
        const int cb = colBase + tx * 4;
        float4 bb0 = *(const float4*)&bz[cb];
        float4 bb1 = *(const float4*)&bz[cb + 64];
        unsigned lo, hi;
        float4 o0, o1;
        UNPACK2(lo, hi, acc2[i][0]); o0.x = __uint_as_float(lo) + bb0.x; o0.y = __uint_as_float(hi) + bb0.y;
        UNPACK2(lo, hi, acc2[i][1]); o0.z = __uint_as_float(lo) + bb0.z; o0.w = __uint_as_float(hi) + bb0.w;
        UNPACK2(lo, hi, acc2[i][2]); o1.x = __uint_as_float(lo) + bb1.x; o1.y = __uint_as_float(hi) + bb1.y;
        UNPACK2(lo, hi, acc2[i][3]); o1.z = __uint_as_float(lo) + bb1.z; o1.w = __uint_as_float(hi) + bb1.w;
        *(float4*)&Cz[(size_t)r * 256 + cb] = o0;
        *(float4*)&Cz[(size_t)r * 256 + cb + 64] = o1;
    }
}

__global__ void k_invnorm() {
    int warp = (blockIdx.x * blockDim.x + threadIdx.x) >> 5;
    int lane = threadIdx.x & 31;
    if (warp >= T_REP * N_NODES) return;
    const float4* r = (const float4*)(g_AF + ((size_t)N_NODES + warp) * 256);
    float4 a = r[lane * 2], b = r[lane * 2 + 1];
    float s = a.x * a.x + a.y * a.y + a.z * a.z + a.w * a.w +
              b.x * b.x + b.y * b.y + b.z * b.z + b.w * b.w;
#pragma unroll
    for (int o = 16; o; o >>= 1) s += __shfl_xor_sync(0xffffffffu, s, o);
    if (lane == 0) g_invn[warp] = 1.f / fmaxf(sqrtf(s), 1e-8f);
}

__device__ __forceinline__ float dot8(float4 f0, float4 f1, float4 a, float4 b) {
    return f0.x * a.x + f0.y * a.y + f0.z * a.z + f0.w * a.w +
           f1.x * b.x + f1.y * b.y + f1.z * b.z + f1.w * b.w;
}

// ---- original-edge CSR (group edges by dst) ----
__global__ void k_ocount(const int* __restrict__ ei) {
    int i = blockIdx.x * blockDim.x + threadIdx.x;
    if (i < N_EDGES) atomicAdd(&g_odeg[ei[N_EDGES + i]], 1);
}

__global__ void k_ofill(const int* __restrict__ ei) {
    int i = blockIdx.x * blockDim.x + threadIdx.x;
    if (i >= N_EDGES) return;
    int d = ei[N_EDGES + i];
    int pos = g_orow[d] + atomicAdd(&g_ocur[d], 1);
    g_oedge[pos] = i;
}

// one warp per dst node: load its 4 replica rows once, iterate incoming edges
__global__ void k_edge_sim2(const int* __restrict__ ei) {
    int d = (blockIdx.x * blockDim.x + threadIdx.x) >> 5;
    if (d >= N_NODES) return;
    int lane = threadIdx.x & 31;
    int len = g_odeg[d];
    if (len == 0) return;
    int start = g_orow[d];
    const float4* t0 = (const float4*)(g_AF + ((size_t)1 * N_NODES + d) * 256);
    const float4* t1 = (const float4*)(g_AF + ((size_t)2 * N_NODES + d) * 256);
    const float4* t2 = (const float4*)(g_AF + ((size_t)3 * N_NODES + d) * 256);
    const float4* t3 = (const float4*)(g_AF + ((size_t)4 * N_NODES + d) * 256);
    float4 a0 = t0[lane * 2], b0 = t0[lane * 2 + 1];
    float4 a1 = t1[lane * 2], b1 = t1[lane * 2 + 1];
    float4 a2 = t2[lane * 2], b2 = t2[lane * 2 + 1];
    float4 a3 = t3[lane * 2], b3 = t3[lane * 2 + 1];
    float i0 = g_invn[d];
    float i1 = g_invn[N_NODES + d];
    float i2 = g_invn[2 * N_NODES + d];
    float i3 = g_invn[3 * N_NODES + d];
    for (int j = 0; j < len; j++) {
        int e = g_oedge[start + j];
        int s = ei[e];
        const float4* fr = (const float4*)(g_AF + (size_t)s * 256);
        float4 f0 = fr[lane * 2], f1 = fr[lane * 2 + 1];
        float p0 = dot8(f0, f1, a0, b0);
        float p1 = dot8(f0, f1, a1, b1);
        float p2 = dot8(f0, f1, a2, b2);
        float p3 = dot8(f0, f1, a3, b3);
#pragma unroll
        for (int o = 16; o; o >>= 1) {
            p0 += __shfl_xor_sync(0xffffffffu, p0, o);
            p1 += __shfl_xor_sync(0xffffffffu, p1, o);
            p2 += __shfl_xor_sync(0xffffffffu, p2, o);
            p3 += __shfl_xor_sync(0xffffffffu, p3, o);
        }
        float s0 = p0 * i0, s1 = p1 * i1, s2 = p2 * i2, s3 = p3 * i3;
        float bv = s0; int bi = 0;
        if (s1 > bv) { bv = s1; bi = 1; }
        if (s2 > bv) { bv = s2; bi = 2; }
        if (s3 > bv) { bv = s3; bi = 3; }
        if (lane == 0) g_best[e] = bi;
    }
}

__global__ void k_deg_init() {
    int i = blockIdx.x * blockDim.x + threadIdx.x;
    if (i < N_TOT) g_deg[i] = 1;   // self loop
}

__device__ __forceinline__ void decode_edge(const int* __restrict__ ei, int i, int& s, int& d) {
    if (i < N_EDGES) {
        s = ei[i]; d = ei[N_EDGES + i];
    } else if (i < 2 * N_EDGES) {
        int e = i - N_EDGES;
        s = ei[e]; d = ei[N_EDGES + e] + g_best[e] * N_NODES;
    } else {
        int r = i - 2 * N_EDGES;
        int rep = r / N_NODES + 1;            // 1..3
        int n = r - (rep - 1) * N_NODES;
        s = n; d = n + rep * N_NODES;
    }
}

__global__ void k_count(const int* __restrict__ ei) {
    int i = blockIdx.x * blockDim.x + threadIdx.x;
    if (i >= NE_TOT) return;
    int s, d;
    decode_edge(ei, i, s, d);
    if (s != d) atomicAdd(&g_deg[d], 1);
}

__global__ void k_dinv() {
    int i = blockIdx.x * blockDim.x + threadIdx.x;
    if (i < N_TOT) g_dinv[i] = rsqrtf((float)g_deg[i]);
}

// ---- generic exclusive scan: out = exscan(in - minus) ----
__global__ void k_scan1(const int* __restrict__ in, int* __restrict__ out, int n, int minus) {
    __shared__ int sm[256];
    int tid = threadIdx.x;
    int base = blockIdx.x * SCAN_BLK;
    int loc[4]; int sum = 0;
#pragma unroll
    for (int u = 0; u < 4; u++) {
        int i = base + tid * 4 + u;
        int v = (i < n) ? (in[i] - minus) : 0;
        loc[u] = sum; sum += v;
    }
    sm[tid] = sum;
    __syncthreads();
    for (int o = 1; o < 256; o <<= 1) {
        int t = (tid >= o) ? sm[tid - o] : 0;
        __syncthreads();
        sm[tid] += t;
        __syncthreads();
    }
    int pre = tid ? sm[tid - 1] : 0;
#pragma unroll
    for (int u = 0; u < 4; u++) {
        int i = base + tid * 4 + u;
        if (i < n) out[i] = pre + loc[u];
    }
    if (tid == 255) g_blocksum[blockIdx.x] = sm[255];
}

__global__ void k_scan2(int nb) {
    __shared__ int sm[256];
    int tid = threadIdx.x;
    sm[tid] = (tid < nb) ? g_blocksum[tid] : 0;
    __syncthreads();
    for (int o = 1; o < 256; o <<= 1) {
        int t = (tid >= o) ? sm[tid - o] : 0;
        __syncthreads();
        sm[tid] += t;
        __syncthreads();
    }
    if (tid < nb) g_blocksum[tid] = tid ? sm[tid - 1] : 0;
}

__global__ void k_scan3(int* __restrict__ out, int n) {
    int i = blockIdx.x * blockDim.x + threadIdx.x;
    if (i < n) out[i] += g_blocksum[i >> 10];
}

__global__ void k_fill(const int* __restrict__ ei) {
    int i = blockIdx.x * blockDim.x + threadIdx.x;
    if (i >= NE_TOT) return;
    int s, d;
    decode_edge(ei, i, s, d);
    if (s == d) return;
    int pos = g_rowptr[d] + atomicAdd(&g_cursor[d], 1);
    g_csr_src[pos] = s;
    g_csr_w[pos] = g_dinv[s] * g_dinv[d];
}

// Out[d] = bias + dinv[d]^2*X[d] + sum_{edges into d} w*X[src]; one warp per row
__global__ void k_aggregate(const float* __restrict__ X, const float* __restrict__ bias,
                            float* __restrict__ Out) {
    int w = (blockIdx.x * blockDim.x + threadIdx.x) >> 5;
    if (w >= N_TOT) return;
    int lane = threadIdx.x & 31;
    int start = g_rowptr[w];
    int len = g_deg[w] - 1;
    float dv = g_dinv[w];
    float ws = dv * dv;
    const float4* xd = (const float4*)(X + (size_t)w * 256);
    float4 sa = xd[lane * 2], sb = xd[lane * 2 + 1];
    float acc0 = ws * sa.x, acc1 = ws * sa.y, acc2 = ws * sa.z, acc3 = ws * sa.w;
    float acc4 = ws * sb.x, acc5 = ws * sb.y, acc6 = ws * sb.z, acc7 = ws * sb.w;
    int j = 0;
    for (; j + 2 <= len; j += 2) {
        int s0 = g_csr_src[start + j];
        int s1 = g_csr_src[start + j + 1];
        float w0 = g_csr_w[start + j];
        float w1 = g_csr_w[start + j + 1];
        const float4* x0 = (const float4*)(X + (size_t)s0 * 256);
        const float4* x1 = (const float4*)(X + (size_t)s1 * 256);
        float4 u0 = x0[lane * 2], v0 = x0[lane * 2 + 1];
        float4 u1 = x1[lane * 2], v1 = x1[lane * 2 + 1];
        acc0 = fmaf(w0, u0.x, acc0); acc1 = fmaf(w0, u0.y, acc1);
        acc2 = fmaf(w0, u0.z, acc2); acc3 = fmaf(w0, u0.w, acc3);
        acc4 = fmaf(w0, v0.x, acc4); acc5 = fmaf(w0, v0.y, acc5);
        acc6 = fmaf(w0, v0.z, acc6); acc7 = fmaf(w0, v0.w, acc7);
        acc0 = fmaf(w1, u1.x, acc0); acc1 = fmaf(w1, u1.y, acc1);
        acc2 = fmaf(w1, u1.z, acc2); acc3 = fmaf(w1, u1.w, acc3);
        acc4 = fmaf(w1, v1.x, acc4); acc5 = fmaf(w1, v1.y, acc5);
        acc6 = fmaf(w1, v1.z, acc6); acc7 = fmaf(w1, v1.w, acc7);
    }
    if (j < len) {
        int s0 = g_csr_src[start + j];
        float w0 = g_csr_w[start + j];
        const float4* x0 = (const float4*)(X + (size_t)s0 * 256);
        float4 u0 = x0[lane * 2], v0 = x0[lane * 2 + 1];
        acc0 = fmaf(w0, u0.x, acc0); acc1 = fmaf(w0, u0.y, acc1);
        acc2 = fmaf(w0, u0.z, acc2); acc3 = fmaf(w0, u0.w, acc3);
        acc4 = fmaf(w0, v0.x, acc4); acc5 = fmaf(w0, v0.y, acc5);
        acc6 = fmaf(w0, v0.z, acc6); acc7 = fmaf(w0, v0.w, acc7);
    }
    const float4* b4 = (const float4*)bias;
    float4 bb0 = b4[lane * 2], bb1 = b4[lane * 2 + 1];
    float4 o0 = make_float4(acc0 + bb0.x, acc1 + bb0.y, acc2 + bb0.z, acc3 + bb0.w);
    float4 o1 = make_float4(acc4 + bb1.x, acc5 + bb1.y, acc6 + bb1.z, acc7 + bb1.w);
    float4* od = (float4*)(Out + (size_t)w * 256);
    od[lane * 2] = o0;
    od[lane * 2 + 1] = o1;
}

// logits = relu(X_row) @ W(256x64) + bias, class = first-argmax over 64.
// W pre-packed in smem across d-pairs; inner loop in f32x2.
__global__ void k_logits(const float* __restrict__ X, const float* __restrict__ W,
                         const float* __restrict__ bias) {
    extern __shared__ float sm[];
    u64* Wp = (u64*)sm;                // 128*64 u64 = 64KB: Wp[d2*64+c] = {W[2d2][c], W[2d2+1][c]}
    float* rbufs = sm + 16384;         // 8 * 256 floats
    int tid = threadIdx.x;
    for (int i = tid; i < 128 * 64; i += 256) {
        int d2 = i >> 6, c = i & 63;
        u64 p;
        PACK2(p, __float_as_uint(W[(2 * d2) * 64 + c]),
                 __float_as_uint(W[(2 * d2 + 1) * 64 + c]));
        Wp[i] = p;
    }
    __syncthreads();
    int warp = tid >> 5, lane = tid & 31;
    float* rbuf = rbufs + warp * 256;
    const u64* xp2 = (const u64*)rbuf;
    for (int row = blockIdx.x * 8 + warp; row < N_TOT; row += gridDim.x * 8) {
        const float4* xr = (const float4*)(X + (size_t)row * 256);
        float4 a = xr[lane * 2], b = xr[lane * 2 + 1];
        a.x = fmaxf(a.x, 0.f); a.y = fmaxf(a.y, 0.f); a.z = fmaxf(a.z, 0.f); a.w = fmaxf(a.w, 0.f);
        b.x = fmaxf(b.x, 0.f); b.y = fmaxf(b.y, 0.f); b.z = fmaxf(b.z, 0.f); b.w = fmaxf(b.w, 0.f);
        ((float4*)rbuf)[lane * 2] = a;
        ((float4*)rbuf)[lane * 2 + 1] = b;
        __syncwarp();
        u64 acc0 = 0ull, acc1 = 0ull;
#pragma unroll 8
        for (int d2 = 0; d2 < 128; d2++) {
            u64 x2 = xp2[d2];
            FMA2(acc0, x2, Wp[d2 * 64 + lane]);
            FMA2(acc1, x2, Wp[d2 * 64 + lane + 32]);
        }
        unsigned lo, hi;
        UNPACK2(lo, hi, acc0);
        float s0 = __uint_as_float(lo) + __uint_as_float(hi) + bias[lane];
        UNPACK2(lo, hi, acc1);
        float s1 = __uint_as_float(lo) + __uint_as_float(hi) + bias[lane + 32];
        float v = s0; int idx = lane;
        if (s1 > v) { v = s1; idx = lane + 32; }
#pragma unroll
        for (int o = 16; o; o >>= 1) {
            float ov = __shfl_xor_sync(0xffffffffu, v, o);
            int oi = __shfl_xor_sync(0xffffffffu, idx, o);
            if (ov > v || (ov == v && oi < idx)) { v = ov; idx = oi; }
        }
        if (lane == 0) g_cls[row] = idx;
        __syncwarp();
    }
}

__global__ void k_H(float* __restrict__ Hout) {
    int n = blockIdx.x * blockDim.x + threadIdx.x;
    if (n >= N_NODES) return;
    int c0 = g_cls[n];
    int c1 = g_cls[N_NODES + n];
    int c2 = g_cls[2 * N_NODES + n];
    int c3 = g_cls[3 * N_NODES + n];
    int c4 = g_cls[4 * N_NODES + n];
    float* o = Hout + (size_t)n * 64;
#pragma unroll
    for (int j = 0; j < 64; j++)
        o[j] = (float)((c0 == j) + (c1 == j) + (c2 == j) + (c3 == j) + (c4 == j));
}

// hf[c,:] += af2[n,:] for each node n with H[n,c] > 0
__global__ void k_hyperedge(const float* __restrict__ Hout, float* __restrict__ hf) {
    extern __shared__ float acc[];   // 16384 floats
    int tid = threadIdx.x;
    for (int i = tid; i < 16384; i += 256) acc[i] = 0.f;
    __syncthreads();
    int warp = tid >> 5, lane = tid & 31;
    for (int n = blockIdx.x * 8 + warp; n < N_NODES; n += gridDim.x * 8) {
        float h0 = Hout[(size_t)n * 64 + lane];
        float h1 = Hout[(size_t)n * 64 + lane + 32];
        unsigned m0 = __ballot_sync(0xffffffffu, h0 > 0.f);
        unsigned m1 = __ballot_sync(0xffffffffu, h1 > 0.f);
        const float4* xr = (const float4*)(g_B + (size_t)n * 256);
        float4 a = xr[lane * 2], b = xr[lane * 2 + 1];
        unsigned mm = m0;
        while (mm) {
            int c = __ffs(mm) - 1; mm &= mm - 1;
            float* p = acc + c * 256 + lane * 8;
            atomicAdd(p + 0, a.x); atomicAdd(p + 1, a.y); atomicAdd(p + 2, a.z); atomicAdd(p + 3, a.w);
            atomicAdd(p + 4, b.x); atomicAdd(p + 5, b.y); atomicAdd(p + 6, b.z); atomicAdd(p + 7, b.w);
        }
        mm = m1;
        while (mm) {
            int c = (__ffs(mm) - 1) + 32; mm &= mm - 1;
            float* p = acc + c * 256 + lane * 8;
            atomicAdd(p + 0, a.x); atomicAdd(p + 1, a.y); atomicAdd(p + 2, a.z); atomicAdd(p + 3, a.w);
            atomicAdd(p + 4, b.x); atomicAdd(p + 5, b.y); atomicAdd(p + 6, b.z); atomicAdd(p + 7, b.w);
        }
    }
    __syncthreads();
    for (int i = tid; i < 16384; i += 256) atomicAdd(&hf[i], acc[i]);
}

// dots[row, c] = (AF_row . hf[c,:]) * 1/16  (f32x2 inner loop)
__global__ void k_dots(const float* __restrict__ hf, float* __restrict__ out) {
    extern __shared__ float sm[];
    u64* Wp = (u64*)sm;                // Wp[d2*64+c] = {hf[c*256+2d2], hf[c*256+2d2+1]}
    float* rbufs = sm + 16384;
    int tid = threadIdx.x;
    for (int i = tid; i < 128 * 64; i += 256) {
        int d2 = i >> 6, c = i & 63;
        u64 p;
        PACK2(p, __float_as_uint(hf[c * 256 + 2 * d2]),
                 __float_as_uint(hf[c * 256 + 2 * d2 + 1]));
        Wp[i] = p;
    }
    __syncthreads();
    int warp = tid >> 5, lane = tid & 31;
    float* rbuf = rbufs + warp * 256;
    const u64* xp2 = (const u64*)rbuf;
    for (int row = blockIdx.x * 8 + warp; row < N_TOT; row += gridDim.x * 8) {
        const float4* xr = (const float4*)(g_AF + (size_t)row * 256);
        ((float4*)rbuf)[lane * 2] = xr[lane * 2];
        ((float4*)rbuf)[lane * 2 + 1] = xr[lane * 2 + 1];
        __syncwarp();
        u64 acc0 = 0ull, acc1 = 0ull;
#pragma unroll 8
        for (int d2 = 0; d2 < 128; d2++) {
            u64 x2 = xp2[d2];
            FMA2(acc0, x2, Wp[d2 * 64 + lane]);
            FMA2(acc1, x2, Wp[d2 * 64 + lane + 32]);
        }
        unsigned lo, hi;
        UNPACK2(lo, hi, acc0);
        float s0 = __uint_as_float(lo) + __uint_as_float(hi);
        UNPACK2(lo, hi, acc1);
        float s1 = __uint_as_float(lo) + __uint_as_float(hi);
        out[(size_t)row * 64 + lane] = s0 * 0.0625f;
        out[(size_t)row * 64 + lane + 32] = s1 * 0.0625f;
        __syncwarp();
    }
}

// ---------------- launch ----------------
extern "C" void kernel_launch(void* const* d_in, const int* in_sizes, int n_in,
                              void* d_out, int out_size) {
    const int*   ei       = (const int*)d_in[0];
    const float* features = (const float*)d_in[1];
    const float* lin_w    = (const float*)d_in[2];
    const float* lin_b    = (const float*)d_in[3];
    const float* gcn0_w   = (const float*)d_in[4];
    const float* gcn0_b   = (const float*)d_in[5];
    const float* gcn1_w   = (const float*)d_in[6];
    const float* gcn1_b   = (const float*)d_in[7];
    const float* lin1_w   = (const float*)d_in[8];
    const float* lin1_b   = (const float*)d_in[9];

    float* out      = (float*)d_out;
    float* H_out    = out;
    float* hf_out   = out + (size_t)N_NODES * NS;
    float* dots_out = hf_out + NS * D;

    float *AF, *X, *B, *ZB;
    int *CUR, *DEG, *ROWPTR, *ODEG, *OROW, *OCUR;
    cudaGetSymbolAddress((void**)&AF, g_AF);
    cudaGetSymbolAddress((void**)&X,  g_X);
    cudaGetSymbolAddress((void**)&B,  g_B);
    cudaGetSymbolAddress((void**)&ZB, g_zerobias);
    cudaGetSymbolAddress((void**)&CUR, g_cursor);
    cudaGetSymbolAddress((void**)&DEG, g_deg);
    cudaGetSymbolAddress((void**)&ROWPTR, g_rowptr);
    cudaGetSymbolAddress((void**)&ODEG, g_odeg);
    cudaGetSymbolAddress((void**)&OROW, g_orow);
    cudaGetSymbolAddress((void**)&OCUR, g_ocur);

    cudaFuncSetAttribute(k_logits,    cudaFuncAttributeMaxDynamicSharedMemorySize, 73728);
    cudaFuncSetAttribute(k_dots,      cudaFuncAttributeMaxDynamicSharedMemorySize, 73728);
    cudaFuncSetAttribute(k_hyperedge, cudaFuncAttributeMaxDynamicSharedMemorySize, 65536);

    const int nb_tot  = (N_TOT + SCAN_BLK - 1) / SCAN_BLK;     // 245
    const int nb_node = (N_NODES + SCAN_BLK - 1) / SCAN_BLK;   // 49

    // 0. original-edge CSR by dst (independent of GEMMs)
    cudaMemsetAsync(ODEG, 0, N_NODES * sizeof(int));
    cudaMemsetAsync(OCUR, 0, N_NODES * sizeof(int));
    k_ocount<<<(N_EDGES + 255) / 256, 256>>>(ei);
    k_scan1<<<nb_node, 256>>>(ODEG, OROW, N_NODES, 0);
    k_scan2<<<1, 256>>>(nb_node);
    k_scan3<<<(N_NODES + 255) / 256, 256>>>(OROW, N_NODES);
    k_ofill<<<(N_EDGES + 255) / 256, 256>>>(ei);

    // 1. assemble all_features (4 heads in one launch via blockIdx.z)
    k_copy_features<<<(N_NODES * D / 4 + 255) / 256, 256>>>((const float4*)features);
    dim3 gN(2, (N_NODES + 127) / 128, 4);
    k_sgemm<0><<<gN, 256>>>(features, lin_w, lin_b,
                            AF + (size_t)N_NODES * 256, N_NODES,
                            65536, N_NODES * 256);

    // 2. per-edge best replica (dst-grouped)
    k_invnorm<<<(T_REP * N_NODES * 32 + 255) / 256, 256>>>();
    k_edge_sim2<<<(N_NODES * 32 + 255) / 256, 256>>>(ei);

    // 3. augmented-graph degrees -> dinv -> CSR
    k_deg_init<<<(N_TOT + 255) / 256, 256>>>();
    k_count<<<(NE_TOT + 255) / 256, 256>>>(ei);
    k_dinv<<<(N_TOT + 255) / 256, 256>>>();
    k_scan1<<<nb_tot, 256>>>(DEG, ROWPTR, N_TOT, 1);
    k_scan2<<<1, 256>>>(nb_tot);
    k_scan3<<<(N_TOT + 255) / 256, 256>>>(ROWPTR, N_TOT);
    cudaMemsetAsync(CUR, 0, N_TOT * sizeof(int));
    k_fill<<<(NE_TOT + 255) / 256, 256>>>(ei);

    // 4. GCN layer 0
    dim3 gT(2, (N_TOT + 127) / 128, 1);
    k_sgemm<1><<<gT, 256>>>(AF, gcn0_w, ZB, X, N_TOT, 0, 0);
    k_aggregate<<<(N_TOT * 32 + 255) / 256, 256>>>(X, gcn0_b, B);

    // 5. GCN layer 1
    k_sgemm<1><<<gT, 256>>>(B, gcn1_w, ZB, X, N_TOT, 0, 0);
    k_aggregate<<<(N_TOT * 32 + 255) / 256, 256>>>(X, gcn1_b, B);

    // 6. logits -> classes -> H
    k_logits<<<2048, 256, 73728>>>(B, lin1_w, lin1_b);
    k_H<<<(N_NODES + 255) / 256, 256>>>(H_out);

    // 7. hyperedge features
    cudaMemsetAsync(hf_out, 0, (size_t)NS * D * sizeof(float));
    k_hyperedge<<<160, 256, 65536>>>(H_out, hf_out);

    // 8. dots
    k_dots<<<2048, 256, 73728>>>(hf_out, dots_out);
}